// round 2
// baseline (speedup 1.0000x reference)
#include <cuda_runtime.h>
#include <math.h>

#define NN 16384
#define NE 262144
#define HH 128
#define BB 64
#define SS 256
#define RR 32

__device__ float g_ie[NE*HH];
__device__ float g_me[NE*HH];
__device__ float g_in[NN*HH];
__device__ float g_P[NN*HH];
__device__ float g_D[NN*HH];
__device__ float g_U[NN*HH];
__device__ float g_mn[NN*HH];
__device__ float g_agg[NN*HH];
__device__ float g_V[NN*HH];
__device__ float g_nodeh[NN*HH];
__device__ float g_msg[NN*HH];
__device__ float g_scratch[NN*384];
__device__ float g_gi[2*NN*384];
__device__ float g_WihT[2*384*128];
__device__ float g_Qrel[RR*HH];
__device__ float g_Qd[2*RR*HH];
__device__ float g_h0[BB*HH];
__device__ float g_y[4*BB*HH];
__device__ int   g_is64[2];

__device__ __forceinline__ int ld_idx(const void* p, long long i, int sel) {
    if (g_is64[sel]) return (int)((const long long*)p)[i];
    return ((const int*)p)[i];
}

__global__ void k_detect(const void* src, const void* et) {
    if (threadIdx.x == 0) {
        const unsigned long long* a = (const unsigned long long*)src;
        int v = 1;
        for (int i = 0; i < 8; i++) if (a[i] >= (unsigned long long)NN) v = 0;
        g_is64[0] = v;
        const unsigned long long* b = (const unsigned long long*)et;
        v = 1;
        for (int i = 0; i < 8; i++) if (b[i] >= (unsigned long long)RR) v = 0;
        g_is64[1] = v;
    }
}

// C[rows,M] = act(A[rows,K] @ W[K,M] + bias); BM=BN=64, BK=16, 256 thr, 4x4 tile
__global__ void k_sgemm(const float* __restrict__ A, const float* __restrict__ W,
                        float* __restrict__ C, int rows, int K, int M,
                        const float* __restrict__ bias, int doRelu)
{
    __shared__ float As[16][64];
    __shared__ float Ws[16][64];
    const int tid = threadIdx.x;
    const int tx = tid & 15, ty = tid >> 4;
    const int row0 = blockIdx.x * 64, col0 = blockIdx.y * 64;
    const int la_r = tid >> 2, la_k = (tid & 3) << 2;
    const int lw_k = tid >> 4, lw_c = (tid & 15) << 2;
    float acc[4][4];
#pragma unroll
    for (int i = 0; i < 4; i++)
#pragma unroll
        for (int j = 0; j < 4; j++) acc[i][j] = 0.f;
    for (int k0 = 0; k0 < K; k0 += 16) {
        float4 av = make_float4(0.f,0.f,0.f,0.f);
        if (row0 + la_r < rows)
            av = *(const float4*)(A + (size_t)(row0 + la_r) * K + (k0 + la_k));
        As[la_k+0][la_r] = av.x; As[la_k+1][la_r] = av.y;
        As[la_k+2][la_r] = av.z; As[la_k+3][la_r] = av.w;
        *(float4*)&Ws[lw_k][lw_c] = *(const float4*)(W + (size_t)(k0+lw_k)*M + col0 + lw_c);
        __syncthreads();
#pragma unroll
        for (int k = 0; k < 16; k++) {
            float4 a4 = *(const float4*)&As[k][ty<<2];
            float4 w4 = *(const float4*)&Ws[k][tx<<2];
            float ar[4] = {a4.x,a4.y,a4.z,a4.w};
            float wr[4] = {w4.x,w4.y,w4.z,w4.w};
#pragma unroll
            for (int i = 0; i < 4; i++)
#pragma unroll
                for (int j = 0; j < 4; j++) acc[i][j] += ar[i]*wr[j];
        }
        __syncthreads();
    }
#pragma unroll
    for (int i = 0; i < 4; i++) {
        int r = row0 + (ty<<2) + i;
        if (r < rows) {
#pragma unroll
            for (int j = 0; j < 4; j++) {
                int c = col0 + (tx<<2) + j;
                float v = acc[i][j];
                if (bias) v += bias[c];
                if (doRelu) v = fmaxf(v, 0.f);
                C[(size_t)r*M + c] = v;
            }
        }
    }
}

__global__ void k_edge_init(const void* srcp, const void* dstp, const void* etp) {
    int t = blockIdx.x*256 + threadIdx.x;     // NE*32 float4s
    int e = t >> 5, j4 = (t & 31) << 2;
    int s = ld_idx(srcp,e,0), dd = ld_idx(dstp,e,0), et = ld_idx(etp,e,1);
    float4 p = *(const float4*)(g_P + (size_t)s*HH + j4);
    float4 q = *(const float4*)(g_Qrel + (size_t)et*HH + j4);
    float4 d = *(const float4*)(g_D + (size_t)dd*HH + j4);
    float4 o;
    o.x = fmaxf(p.x+q.x+d.x, 0.f); o.y = fmaxf(p.y+q.y+d.y, 0.f);
    o.z = fmaxf(p.z+q.z+d.z, 0.f); o.w = fmaxf(p.w+q.w+d.w, 0.f);
    *(float4*)(g_ie + (size_t)e*HH + j4) = o;
}

// hidden = X@Wm (+addvec[idx]); a = sigmoid(relu(hidden)·w2)
// mode 0: out = ie * a ;  mode 1: out = relu(ie + a * V[src])
__global__ void k_edge_att(const float* __restrict__ X, const float* __restrict__ Wm,
                           const float* __restrict__ addvec, const void* idx_add, int sel_add,
                           const void* idx_src, const float* __restrict__ w2,
                           const float* __restrict__ ie, const float* __restrict__ V,
                           float* __restrict__ outp, int mode)
{
    __shared__ float Xs[16][64];
    __shared__ float Ws2[16][128];
    const int tid = threadIdx.x;
    const int tx = tid & 15, ty = tid >> 4;
    const int e0 = blockIdx.x * 64;
    const int la_r = tid >> 2, la_k = (tid & 3) << 2;
    float acc[4][8];
#pragma unroll
    for (int i = 0; i < 4; i++)
#pragma unroll
        for (int j = 0; j < 8; j++) acc[i][j] = 0.f;
    for (int k0 = 0; k0 < 128; k0 += 16) {
        float4 av = *(const float4*)(X + (size_t)(e0+la_r)*HH + k0 + la_k);
        Xs[la_k+0][la_r] = av.x; Xs[la_k+1][la_r] = av.y;
        Xs[la_k+2][la_r] = av.z; Xs[la_k+3][la_r] = av.w;
#pragma unroll
        for (int p = 0; p < 2; p++) {
            int q = tid + p*256;
            int kk = q >> 5, cc = (q & 31) << 2;
            *(float4*)&Ws2[kk][cc] = *(const float4*)(Wm + (size_t)(k0+kk)*HH + cc);
        }
        __syncthreads();
#pragma unroll
        for (int k = 0; k < 16; k++) {
            float4 a4 = *(const float4*)&Xs[k][ty<<2];
            float4 w0 = *(const float4*)&Ws2[k][tx*8];
            float4 w1 = *(const float4*)&Ws2[k][tx*8+4];
            float ar[4] = {a4.x,a4.y,a4.z,a4.w};
            float wr[8] = {w0.x,w0.y,w0.z,w0.w,w1.x,w1.y,w1.z,w1.w};
#pragma unroll
            for (int i = 0; i < 4; i++)
#pragma unroll
                for (int j = 0; j < 8; j++) acc[i][j] += ar[i]*wr[j];
        }
        __syncthreads();
    }
    const int lane = tid & 31;
    float w2v[8];
    *(float4*)&w2v[0] = *(const float4*)(w2 + tx*8);
    *(float4*)&w2v[4] = *(const float4*)(w2 + tx*8 + 4);
    float a_s[4];
#pragma unroll
    for (int i = 0; i < 4; i++) {
        int e = e0 + (ty<<2) + i;
        int ia = ld_idx(idx_add, e, sel_add);
        float4 d0 = *(const float4*)(addvec + (size_t)ia*HH + tx*8);
        float4 d1 = *(const float4*)(addvec + (size_t)ia*HH + tx*8 + 4);
        float adr[8] = {d0.x,d0.y,d0.z,d0.w,d1.x,d1.y,d1.z,d1.w};
        float ps = 0.f;
#pragma unroll
        for (int j = 0; j < 8; j++) ps += fmaxf(acc[i][j] + adr[j], 0.f) * w2v[j];
#pragma unroll
        for (int off = 8; off; off >>= 1)
            ps += __shfl_down_sync(0xffffffffu, ps, off, 16);
        ps = __shfl_sync(0xffffffffu, ps, lane & 16, 32);
        a_s[i] = 1.f / (1.f + expf(-ps));
    }
#pragma unroll
    for (int i = 0; i < 4; i++) {
        int e = e0 + (ty<<2) + i;
        size_t base = (size_t)e*HH + tx*8;
        float4 i0 = *(const float4*)(ie + base);
        float4 i1 = *(const float4*)(ie + base + 4);
        float4 o0, o1;
        float a = a_s[i];
        if (mode == 0) {
            o0 = make_float4(i0.x*a, i0.y*a, i0.z*a, i0.w*a);
            o1 = make_float4(i1.x*a, i1.y*a, i1.z*a, i1.w*a);
        } else {
            int s = ld_idx(idx_src, e, 0);
            float4 v0 = *(const float4*)(V + (size_t)s*HH + tx*8);
            float4 v1 = *(const float4*)(V + (size_t)s*HH + tx*8 + 4);
            o0.x = fmaxf(i0.x + a*v0.x, 0.f); o0.y = fmaxf(i0.y + a*v0.y, 0.f);
            o0.z = fmaxf(i0.z + a*v0.z, 0.f); o0.w = fmaxf(i0.w + a*v0.w, 0.f);
            o1.x = fmaxf(i1.x + a*v1.x, 0.f); o1.y = fmaxf(i1.y + a*v1.y, 0.f);
            o1.z = fmaxf(i1.z + a*v1.z, 0.f); o1.w = fmaxf(i1.w + a*v1.w, 0.f);
        }
        *(float4*)(outp + base)     = o0;
        *(float4*)(outp + base + 4) = o1;
    }
}

__global__ void k_zero(float* p, int n4) {
    int t = blockIdx.x*256 + threadIdx.x;
    if (t < n4) *(float4*)(p + (size_t)t*4) = make_float4(0.f,0.f,0.f,0.f);
}

__global__ void k_scatter(const float* __restrict__ me, const void* dstp) {
    int t = blockIdx.x*256 + threadIdx.x;  // NE*32 float4s
    int e = t >> 5, j4 = (t & 31) << 2;
    int dd = ld_idx(dstp, e, 0);
    float4 v = *(const float4*)(me + (size_t)e*HH + j4);
    float* a = g_agg + (size_t)dd*HH + j4;
    atomicAdd(a+0, v.x); atomicAdd(a+1, v.y);
    atomicAdd(a+2, v.z); atomicAdd(a+3, v.w);
}

__global__ void k_add2(const float* a, const float* b, float* o, int n) {
    int t = blockIdx.x*256 + threadIdx.x;
    if (t < n) o[t] = a[t] + b[t];
}

__global__ void k_concat3() {   // scratch[N,384] = [agg | mn | in]
    int t = blockIdx.x*256 + threadIdx.x;
    int r = t / 384, j = t % 384;
    float v;
    if (j < 128)      v = g_agg[(size_t)r*128 + j];
    else if (j < 256) v = g_mn[(size_t)r*128 + j - 128];
    else              v = g_in[(size_t)r*128 + j - 256];
    g_scratch[t] = v;
}

__global__ void k_msg(const float* __restrict__ gru_bias) {
    int t = blockIdx.x*256 + threadIdx.x;
    g_msg[t] = fmaxf(g_nodeh[t] + gru_bias[t & 127], 0.f);
}

__global__ void k_h0() {
    int b = blockIdx.x, j = threadIdx.x;
    float m = -1e30f;
    for (int s = 0; s < SS; s++)
        m = fmaxf(m, g_nodeh[((size_t)(b*SS + s))*HH + j]);
    g_h0[b*HH + j] = m;
}

__global__ void k_twih(const float* __restrict__ Wih) {
    int t = blockIdx.x*256 + threadIdx.x;
    if (t < 2*384*128) {
        int d = t / (384*128), rem = t % (384*128);
        int o = rem / 128, k = rem % 128;
        g_WihT[d*384*128 + k*384 + o] = Wih[t];
    }
}

__global__ void __launch_bounds__(384) k_gru(const float* __restrict__ Whh,
                                             const float* __restrict__ bhh)
{
    const int b = blockIdx.x, dir = blockIdx.y;
    const int o = threadIdx.x;
    float w[128];
    const float* wr = Whh + ((size_t)dir*384 + o)*128;
#pragma unroll
    for (int k = 0; k < 128; k += 4) {
        float4 v = *(const float4*)(wr + k);
        w[k]=v.x; w[k+1]=v.y; w[k+2]=v.z; w[k+3]=v.w;
    }
    const float bh = bhh[dir*384 + o];
    __shared__ float h_s[128];
    __shared__ float gh_s[384];
    if (o < 128) h_s[o] = g_h0[b*128 + o];
    __syncthreads();
    const float* gi = g_gi + (size_t)dir*NN*384;
    const int nsteps = (dir == 0) ? 2 : SS;
    for (int i2 = 0; i2 < nsteps; i2++) {
        int t = (dir == 0) ? i2 : (SS - 1 - i2);
        float gh = bh;
#pragma unroll
        for (int k = 0; k < 128; k += 4) {
            float4 hv = *(const float4*)&h_s[k];
            gh += w[k]*hv.x + w[k+1]*hv.y + w[k+2]*hv.z + w[k+3]*hv.w;
        }
        gh_s[o] = gh;
        __syncthreads();
        if (o < 128) {
            size_t gb = ((size_t)(b*SS + t))*384;
            float ir = gi[gb+o], iz = gi[gb+128+o], inn = gi[gb+256+o];
            float r = 1.f/(1.f+expf(-(ir + gh_s[o])));
            float z = 1.f/(1.f+expf(-(iz + gh_s[128+o])));
            float n = tanhf(inn + r*gh_s[256+o]);
            float hnew = (1.f-z)*n + z*h_s[o];
            if (dir == 0) {
                if (i2 == 0)      g_y[0*BB*128 + b*128 + o] = hnew;
                else if (i2 == 1) g_y[1*BB*128 + b*128 + o] = hnew;
            } else {
                if (i2 == SS-1)      g_y[2*BB*128 + b*128 + o] = hnew;
                else if (i2 == SS-2) g_y[3*BB*128 + b*128 + o] = hnew;
            }
            h_s[o] = hnew;
        }
        __syncthreads();
    }
}

__global__ void k_final(const float* __restrict__ Wo, const float* __restrict__ bo,
                        const float* __restrict__ rel_emb, const void* trg,
                        const float* __restrict__ l1W, const float* __restrict__ l1b,
                        const float* __restrict__ l2W, const float* __restrict__ l2b,
                        float* __restrict__ out)
{
    const int b = blockIdx.x, j = threadIdx.x;
    __shared__ float conv[128];
    __shared__ float s16[16];
    float hh = bo[j], ht = bo[j];
    const float* yf0 = g_y + 0*BB*128 + b*128;
    const float* yf1 = g_y + 1*BB*128 + b*128;
    const float* yb0 = g_y + 2*BB*128 + b*128;
    const float* yb1 = g_y + 3*BB*128 + b*128;
    for (int k = 0; k < 128; k++) {
        float wk = Wo[k*128 + j];
        hh += yf0[k]*wk; ht += yf1[k]*wk;
    }
    for (int k = 0; k < 128; k++) {
        float wk = Wo[(128+k)*128 + j];
        hh += yb0[k]*wk; ht += yb1[k]*wk;
    }
    hh = fmaxf(hh, 0.f); ht = fmaxf(ht, 0.f);
    int tr = ld_idx(trg, b, 1);
    conv[j] = tanhf(hh + rel_emb[tr*128 + j] - ht);
    __syncthreads();
    if (j < 16) {
        float s = l1b[j];
        for (int k = 0; k < 128; k++) s += conv[k]*l1W[k*16 + j];
        s16[j] = s;
    }
    __syncthreads();
    if (j == 0) {
        float o = l2b[0];
        for (int i = 0; i < 16; i++) o += s16[i]*l2W[i];
        out[b] = o;
    }
}

extern "C" void kernel_launch(void* const* d_in, const int* in_sizes, int n_in,
                              void* d_out, int out_size)
{
    const float* node_feat = (const float*)d_in[0];
    const float* rel_emb   = (const float*)d_in[1];
    const float* W_i_node  = (const float*)d_in[2];
    const float* W_i_edge  = (const float*)d_in[3];
    const float* W_att_in1 = (const float*)d_in[4];
    const float* W_att_in2 = (const float*)d_in[5];
    const float* W_h_node  = (const float*)d_in[6];
    const float* W_h_edge  = (const float*)d_in[7];
    const float* W_att1    = (const float*)d_in[8];
    const float* W_att2    = (const float*)d_in[9];
    const float* comm_W    = (const float*)d_in[10];
    const float* W_o       = (const float*)d_in[11];
    const float* b_o       = (const float*)d_in[12];
    const float* gru_bias  = (const float*)d_in[13];
    const float* gru_Wih   = (const float*)d_in[14];
    const float* gru_Whh   = (const float*)d_in[15];
    const float* gru_bih   = (const float*)d_in[16];
    const float* gru_bhh   = (const float*)d_in[17];
    const float* lin1_W    = (const float*)d_in[18];
    const float* lin1_b    = (const float*)d_in[19];
    const float* lin2_W    = (const float*)d_in[20];
    const float* lin2_b    = (const float*)d_in[21];
    const void*  src       = d_in[22];
    const void*  dst       = d_in[23];
    const void*  etype     = d_in[24];
    const void*  elabel    = d_in[25];
    const void*  trg       = d_in[26];
    float* out = (float*)d_out;

    float *ge_ie, *ge_me, *ge_in, *ge_P, *ge_D, *ge_U, *ge_mn, *ge_agg, *ge_V;
    float *ge_nodeh, *ge_msg, *ge_scr, *ge_gi, *ge_WihT, *ge_Qrel, *ge_Qd;
    cudaGetSymbolAddress((void**)&ge_ie, g_ie);
    cudaGetSymbolAddress((void**)&ge_me, g_me);
    cudaGetSymbolAddress((void**)&ge_in, g_in);
    cudaGetSymbolAddress((void**)&ge_P, g_P);
    cudaGetSymbolAddress((void**)&ge_D, g_D);
    cudaGetSymbolAddress((void**)&ge_U, g_U);
    cudaGetSymbolAddress((void**)&ge_mn, g_mn);
    cudaGetSymbolAddress((void**)&ge_agg, g_agg);
    cudaGetSymbolAddress((void**)&ge_V, g_V);
    cudaGetSymbolAddress((void**)&ge_nodeh, g_nodeh);
    cudaGetSymbolAddress((void**)&ge_msg, g_msg);
    cudaGetSymbolAddress((void**)&ge_scr, g_scratch);
    cudaGetSymbolAddress((void**)&ge_gi, g_gi);
    cudaGetSymbolAddress((void**)&ge_WihT, g_WihT);
    cudaGetSymbolAddress((void**)&ge_Qrel, g_Qrel);
    cudaGetSymbolAddress((void**)&ge_Qd, g_Qd);

    k_detect<<<1, 32>>>(src, etype);

    dim3 gN(NN/64, 2);   // node GEMM M=128
    // P, D, Qrel, input_node
    k_sgemm<<<gN, 256>>>(node_feat, W_i_edge,          ge_P, NN, 64, 128, NULL, 0);
    k_sgemm<<<gN, 256>>>(node_feat, W_i_edge + 192*128, ge_D, NN, 64, 128, NULL, 0);
    k_sgemm<<<dim3(1,2), 256>>>(rel_emb, W_i_edge + 64*128, ge_Qrel, RR, 128, 128, NULL, 0);
    k_sgemm<<<gN, 256>>>(node_feat, W_i_node, ge_in, NN, 64, 128, NULL, 1);
    // Qd for both depths
    k_sgemm<<<dim3(1,2), 256>>>(rel_emb, W_att1 + 128*128,          ge_Qd,            RR, 128, 128, NULL, 0);
    k_sgemm<<<dim3(1,2), 256>>>(rel_emb, W_att1 + 32768 + 128*128,  ge_Qd + RR*128,   RR, 128, 128, NULL, 0);

    k_edge_init<<<NE*32/256, 256>>>(src, dst, etype);

    // input attention: U = in @ W_att_in1_top ; me = ie * sigmoid(...)
    k_sgemm<<<gN, 256>>>(ge_in, W_att_in1, ge_U, NN, 128, 128, NULL, 0);
    k_edge_att<<<NE/64, 256>>>(ge_ie, W_att_in1 + 128*128, ge_U, src, 0, src,
                               W_att_in2, ge_ie, NULL, ge_me, 0);

    // two message-passing depths
    for (int d = 0; d < 2; d++) {
        const float* mn_old = (d == 0) ? ge_in : ge_mn;
        k_zero<<<NN*128/4/256, 256>>>(ge_agg, NN*128/4);
        k_scatter<<<NE*32/256, 256>>>(ge_me, dst);
        k_add2<<<NN*128/256, 256>>>(mn_old, ge_agg, ge_scr, NN*128);
        k_sgemm<<<gN, 256>>>(ge_scr, W_h_node + d*16384, ge_mn, NN, 128, 128, NULL, 1);
        k_sgemm<<<gN, 256>>>(ge_mn, W_h_edge + d*16384, ge_V, NN, 128, 128, NULL, 0);
        k_edge_att<<<NE/64, 256>>>(ge_me, W_att1 + d*32768, ge_Qd + d*RR*128, elabel, 1,
                                   src, W_att2 + d*128, ge_ie, ge_V, ge_me, 1);
    }

    // readout: agg, concat, comm_W
    k_zero<<<NN*128/4/256, 256>>>(ge_agg, NN*128/4);
    k_scatter<<<NE*32/256, 256>>>(ge_me, dst);
    k_concat3<<<NN*384/256, 256>>>();
    k_sgemm<<<gN, 256>>>(ge_scr, comm_W, ge_nodeh, NN, 384, 128, NULL, 0);

    // GRU
    k_msg<<<NN*128/256, 256>>>(gru_bias);
    k_h0<<<BB, 128>>>();
    k_twih<<<(2*384*128 + 255)/256, 256>>>(gru_Wih);
    k_sgemm<<<dim3(NN/64, 6), 256>>>(ge_msg, ge_WihT,           ge_gi,            NN, 128, 384, gru_bih,       0);
    k_sgemm<<<dim3(NN/64, 6), 256>>>(ge_msg, ge_WihT + 384*128, ge_gi + (size_t)NN*384, NN, 128, 384, gru_bih + 384, 0);
    k_gru<<<dim3(BB, 2), 384>>>(gru_Whh, gru_bhh);

    k_final<<<BB, 128>>>(W_o, b_o, rel_emb, trg, lin1_W, lin1_b, lin2_W, lin2_b, out);
}

// round 5
// speedup vs baseline: 1.2731x; 1.2731x over previous
#include <cuda_runtime.h>
#include <math.h>

#define NN 16384
#define NE 262144
#define HH 128
#define BB 64
#define SS 256
#define RR 32

__device__ float g_ie[NE*HH];
__device__ float g_me[NE*HH];
__device__ float g_in[NN*HH];
__device__ float g_P[NN*HH];
__device__ float g_D[NN*HH];
__device__ float g_U[NN*HH];
__device__ float g_mn[NN*HH];
__device__ float g_agg[NN*HH];
__device__ float g_V[NN*HH];
__device__ float g_nodeh[NN*HH];
__device__ float g_msg[NN*HH];
__device__ float g_scratch[NN*384];
__device__ float g_gi[2*NN*384];
__device__ float g_WihT[2*384*128];
__device__ float g_Qrel[RR*HH];
__device__ float g_Qd[2*RR*HH];
__device__ float g_h0[BB*HH];
__device__ float g_y[4*BB*HH];
__device__ int   g_is64[2];

__device__ __forceinline__ int ld_idx(const void* p, long long i, int sel) {
    if (g_is64[sel]) return (int)((const long long*)p)[i];
    return ((const int*)p)[i];
}

__global__ void k_detect(const void* src, const void* et) {
    if (threadIdx.x == 0) {
        const unsigned long long* a = (const unsigned long long*)src;
        int v = 1;
        for (int i = 0; i < 8; i++) if (a[i] >= (unsigned long long)NN) v = 0;
        g_is64[0] = v;
        const unsigned long long* b = (const unsigned long long*)et;
        v = 1;
        for (int i = 0; i < 8; i++) if (b[i] >= (unsigned long long)RR) v = 0;
        g_is64[1] = v;
    }
}

// ---------- tf32 helpers ----------
__device__ __forceinline__ void f2tf(float x, float& hi, float& lo) {
    unsigned h;
    asm("cvt.rna.tf32.f32 %0, %1;" : "=r"(h) : "f"(x));
    float hf = __uint_as_float(h);
    unsigned l;
    asm("cvt.rna.tf32.f32 %0, %1;" : "=r"(l) : "f"(x - hf));
    hi = hf; lo = __uint_as_float(l);
}

__device__ __forceinline__ void mma8(float* d, const unsigned* a, const unsigned* b) {
    asm volatile("mma.sync.aligned.m16n8k8.row.col.f32.tf32.tf32.f32 "
        "{%0,%1,%2,%3}, {%4,%5,%6,%7}, {%8,%9}, {%0,%1,%2,%3};"
        : "+f"(d[0]), "+f"(d[1]), "+f"(d[2]), "+f"(d[3])
        : "r"(a[0]), "r"(a[1]), "r"(a[2]), "r"(a[3]), "r"(b[0]), "r"(b[1]));
}

// dynamic smem layout (floats): Ah[128*36], Al[128*36], Wh[32*136], Wl[32*136]
#define SM_AL 4608
#define SM_WH 9216
#define SM_WL 13568
#define SM_BYTES ((13568 + 32*136) * 4)

// ---------- tensor-core GEMM: C[rows,M] = act(A[rows,K]@W[K,M]+bias) ----------
__global__ void __launch_bounds__(256) k_tgemm(
    const float* __restrict__ A, const float* __restrict__ W, float* __restrict__ C,
    int K, int M, const float* __restrict__ bias, int doRelu)
{
    extern __shared__ float sm[];
    float *Ah = sm, *Al = sm + SM_AL, *Wh = sm + SM_WH, *Wl = sm + SM_WL;
    const int tid = threadIdx.x;
    const int w = tid >> 5, lane = tid & 31;
    const int g = lane >> 2, t = lane & 3;
    const int wr0 = (w >> 1) * 32, wc0 = (w & 1) * 64;
    const long long row0 = (long long)blockIdx.x * 128;
    const int col0 = blockIdx.y * 128;

    float acc[2][8][4];
#pragma unroll
    for (int a = 0; a < 2; a++)
#pragma unroll
        for (int b = 0; b < 8; b++)
#pragma unroll
            for (int c = 0; c < 4; c++) acc[a][b][c] = 0.f;

    for (int k0 = 0; k0 < K; k0 += 32) {
        __syncthreads();
#pragma unroll
        for (int i = 0; i < 4; i++) {
            int f = tid + 256 * i;
            int r = f >> 3, j = (f & 7) << 2;
            float4 v = *(const float4*)(A + (row0 + r) * K + k0 + j);
            float h, l;
            f2tf(v.x, h, l); Ah[r*36+j+0] = h; Al[r*36+j+0] = l;
            f2tf(v.y, h, l); Ah[r*36+j+1] = h; Al[r*36+j+1] = l;
            f2tf(v.z, h, l); Ah[r*36+j+2] = h; Al[r*36+j+2] = l;
            f2tf(v.w, h, l); Ah[r*36+j+3] = h; Al[r*36+j+3] = l;
        }
#pragma unroll
        for (int i = 0; i < 4; i++) {
            int f = tid + 256 * i;
            int kk = f >> 5, c = (f & 31) << 2;
            float4 v = *(const float4*)(W + (long long)(k0 + kk) * M + col0 + c);
            float h, l;
            f2tf(v.x, h, l); Wh[kk*136+c+0] = h; Wl[kk*136+c+0] = l;
            f2tf(v.y, h, l); Wh[kk*136+c+1] = h; Wl[kk*136+c+1] = l;
            f2tf(v.z, h, l); Wh[kk*136+c+2] = h; Wl[kk*136+c+2] = l;
            f2tf(v.w, h, l); Wh[kk*136+c+3] = h; Wl[kk*136+c+3] = l;
        }
        __syncthreads();
#pragma unroll
        for (int ks = 0; ks < 32; ks += 8) {
            unsigned ah[2][4], al[2][4];
#pragma unroll
            for (int mt = 0; mt < 2; mt++) {
                int rb = wr0 + mt * 16 + g;
                ah[mt][0] = __float_as_uint(Ah[rb*36 + ks + t]);
                ah[mt][1] = __float_as_uint(Ah[(rb+8)*36 + ks + t]);
                ah[mt][2] = __float_as_uint(Ah[rb*36 + ks + t + 4]);
                ah[mt][3] = __float_as_uint(Ah[(rb+8)*36 + ks + t + 4]);
                al[mt][0] = __float_as_uint(Al[rb*36 + ks + t]);
                al[mt][1] = __float_as_uint(Al[(rb+8)*36 + ks + t]);
                al[mt][2] = __float_as_uint(Al[rb*36 + ks + t + 4]);
                al[mt][3] = __float_as_uint(Al[(rb+8)*36 + ks + t + 4]);
            }
#pragma unroll
            for (int nt = 0; nt < 8; nt++) {
                int cn = wc0 + nt * 8 + g;
                unsigned bh[2], bl[2];
                bh[0] = __float_as_uint(Wh[(ks+t)*136 + cn]);
                bh[1] = __float_as_uint(Wh[(ks+t+4)*136 + cn]);
                bl[0] = __float_as_uint(Wl[(ks+t)*136 + cn]);
                bl[1] = __float_as_uint(Wl[(ks+t+4)*136 + cn]);
#pragma unroll
                for (int mt = 0; mt < 2; mt++) {
                    mma8(acc[mt][nt], ah[mt], bh);
                    mma8(acc[mt][nt], ah[mt], bl);
                    mma8(acc[mt][nt], al[mt], bh);
                }
            }
        }
    }
#pragma unroll
    for (int mt = 0; mt < 2; mt++) {
#pragma unroll
        for (int nt = 0; nt < 8; nt++) {
            int c = col0 + wc0 + nt * 8 + t * 2;
            long long r0 = row0 + wr0 + mt * 16 + g;
            float b0 = bias ? bias[c] : 0.f, b1 = bias ? bias[c+1] : 0.f;
            float v0 = acc[mt][nt][0] + b0, v1 = acc[mt][nt][1] + b1;
            float v2 = acc[mt][nt][2] + b0, v3 = acc[mt][nt][3] + b1;
            if (doRelu) {
                v0 = fmaxf(v0, 0.f); v1 = fmaxf(v1, 0.f);
                v2 = fmaxf(v2, 0.f); v3 = fmaxf(v3, 0.f);
            }
            *(float2*)(C + r0 * M + c)       = make_float2(v0, v1);
            *(float2*)(C + (r0 + 8) * M + c) = make_float2(v2, v3);
        }
    }
}

// ---------- small SIMT GEMM kept for 32-row rel_emb GEMMs ----------
__global__ void k_sgemm(const float* __restrict__ A, const float* __restrict__ W,
                        float* __restrict__ C, int rows, int K, int M,
                        const float* __restrict__ bias, int doRelu)
{
    __shared__ float As[16][64];
    __shared__ float Ws[16][64];
    const int tid = threadIdx.x;
    const int tx = tid & 15, ty = tid >> 4;
    const int row0 = blockIdx.x * 64, col0 = blockIdx.y * 64;
    const int la_r = tid >> 2, la_k = (tid & 3) << 2;
    const int lw_k = tid >> 4, lw_c = (tid & 15) << 2;
    float acc[4][4];
#pragma unroll
    for (int i = 0; i < 4; i++)
#pragma unroll
        for (int j = 0; j < 4; j++) acc[i][j] = 0.f;
    for (int k0 = 0; k0 < K; k0 += 16) {
        float4 av = make_float4(0.f,0.f,0.f,0.f);
        if (row0 + la_r < rows)
            av = *(const float4*)(A + (size_t)(row0 + la_r) * K + (k0 + la_k));
        As[la_k+0][la_r] = av.x; As[la_k+1][la_r] = av.y;
        As[la_k+2][la_r] = av.z; As[la_k+3][la_r] = av.w;
        *(float4*)&Ws[lw_k][lw_c] = *(const float4*)(W + (size_t)(k0+lw_k)*M + col0 + lw_c);
        __syncthreads();
#pragma unroll
        for (int k = 0; k < 16; k++) {
            float4 a4 = *(const float4*)&As[k][ty<<2];
            float4 w4 = *(const float4*)&Ws[k][tx<<2];
            float ar[4] = {a4.x,a4.y,a4.z,a4.w};
            float wr[4] = {w4.x,w4.y,w4.z,w4.w};
#pragma unroll
            for (int i = 0; i < 4; i++)
#pragma unroll
                for (int j = 0; j < 4; j++) acc[i][j] += ar[i]*wr[j];
        }
        __syncthreads();
    }
#pragma unroll
    for (int i = 0; i < 4; i++) {
        int r = row0 + (ty<<2) + i;
        if (r < rows) {
#pragma unroll
            for (int j = 0; j < 4; j++) {
                int c = col0 + (tx<<2) + j;
                float v = acc[i][j];
                if (bias) v += bias[c];
                if (doRelu) v = fmaxf(v, 0.f);
                C[(size_t)r*M + c] = v;
            }
        }
    }
}

__global__ void k_edge_init(const void* srcp, const void* dstp, const void* etp) {
    int t = blockIdx.x*256 + threadIdx.x;
    int e = t >> 5, j4 = (t & 31) << 2;
    int s = ld_idx(srcp,e,0), dd = ld_idx(dstp,e,0), et = ld_idx(etp,e,1);
    float4 p = *(const float4*)(g_P + (size_t)s*HH + j4);
    float4 q = *(const float4*)(g_Qrel + (size_t)et*HH + j4);
    float4 d = *(const float4*)(g_D + (size_t)dd*HH + j4);
    float4 o;
    o.x = fmaxf(p.x+q.x+d.x, 0.f); o.y = fmaxf(p.y+q.y+d.y, 0.f);
    o.z = fmaxf(p.z+q.z+d.z, 0.f); o.w = fmaxf(p.w+q.w+d.w, 0.f);
    *(float4*)(g_ie + (size_t)e*HH + j4) = o;
}

// ---------- tensor-core fused edge attention ----------
__global__ void __launch_bounds__(256) k_edge_att_tc(
    const float* __restrict__ X, const float* __restrict__ Wm,
    const float* __restrict__ addvec, const void* idx_add, int sel_add,
    const void* idx_src, const float* __restrict__ w2,
    const float* __restrict__ ie, const float* __restrict__ V,
    float* __restrict__ outp, int mode)
{
    extern __shared__ float sm[];
    float *Ah = sm, *Al = sm + SM_AL, *Wh = sm + SM_WH, *Wl = sm + SM_WL;
    __shared__ int ia_s[128], is_s[128];
    __shared__ float a_s[128], part_s[256], w2_s[128];

    const int tid = threadIdx.x;
    const int w = tid >> 5, lane = tid & 31;
    const int g = lane >> 2, t = lane & 3;
    const int wr0 = (w >> 1) * 32, wc0 = (w & 1) * 64;
    const long long e0 = (long long)blockIdx.x * 128;

    if (tid < 128) {
        ia_s[tid] = ld_idx(idx_add, e0 + tid, sel_add);
        is_s[tid] = ld_idx(idx_src, e0 + tid, 0);
        w2_s[tid] = w2[tid];
    }

    float acc[2][8][4];
#pragma unroll
    for (int a = 0; a < 2; a++)
#pragma unroll
        for (int b = 0; b < 8; b++)
#pragma unroll
            for (int c = 0; c < 4; c++) acc[a][b][c] = 0.f;

    for (int k0 = 0; k0 < 128; k0 += 32) {
        __syncthreads();
#pragma unroll
        for (int i = 0; i < 4; i++) {
            int f = tid + 256 * i;
            int r = f >> 3, j = (f & 7) << 2;
            float4 v = *(const float4*)(X + (e0 + r) * HH + k0 + j);
            float h, l;
            f2tf(v.x, h, l); Ah[r*36+j+0] = h; Al[r*36+j+0] = l;
            f2tf(v.y, h, l); Ah[r*36+j+1] = h; Al[r*36+j+1] = l;
            f2tf(v.z, h, l); Ah[r*36+j+2] = h; Al[r*36+j+2] = l;
            f2tf(v.w, h, l); Ah[r*36+j+3] = h; Al[r*36+j+3] = l;
        }
#pragma unroll
        for (int i = 0; i < 4; i++) {
            int f = tid + 256 * i;
            int kk = f >> 5, c = (f & 31) << 2;
            float4 v = *(const float4*)(Wm + (long long)(k0 + kk) * HH + c);
            float h, l;
            f2tf(v.x, h, l); Wh[kk*136+c+0] = h; Wl[kk*136+c+0] = l;
            f2tf(v.y, h, l); Wh[kk*136+c+1] = h; Wl[kk*136+c+1] = l;
            f2tf(v.z, h, l); Wh[kk*136+c+2] = h; Wl[kk*136+c+2] = l;
            f2tf(v.w, h, l); Wh[kk*136+c+3] = h; Wl[kk*136+c+3] = l;
        }
        __syncthreads();
#pragma unroll
        for (int ks = 0; ks < 32; ks += 8) {
            unsigned ah[2][4], al[2][4];
#pragma unroll
            for (int mt = 0; mt < 2; mt++) {
                int rb = wr0 + mt * 16 + g;
                ah[mt][0] = __float_as_uint(Ah[rb*36 + ks + t]);
                ah[mt][1] = __float_as_uint(Ah[(rb+8)*36 + ks + t]);
                ah[mt][2] = __float_as_uint(Ah[rb*36 + ks + t + 4]);
                ah[mt][3] = __float_as_uint(Ah[(rb+8)*36 + ks + t + 4]);
                al[mt][0] = __float_as_uint(Al[rb*36 + ks + t]);
                al[mt][1] = __float_as_uint(Al[(rb+8)*36 + ks + t]);
                al[mt][2] = __float_as_uint(Al[rb*36 + ks + t + 4]);
                al[mt][3] = __float_as_uint(Al[(rb+8)*36 + ks + t + 4]);
            }
#pragma unroll
            for (int nt = 0; nt < 8; nt++) {
                int cn = wc0 + nt * 8 + g;
                unsigned bh[2], bl[2];
                bh[0] = __float_as_uint(Wh[(ks+t)*136 + cn]);
                bh[1] = __float_as_uint(Wh[(ks+t+4)*136 + cn]);
                bl[0] = __float_as_uint(Wl[(ks+t)*136 + cn]);
                bl[1] = __float_as_uint(Wl[(ks+t+4)*136 + cn]);
#pragma unroll
                for (int mt = 0; mt < 2; mt++) {
                    mma8(acc[mt][nt], ah[mt], bh);
                    mma8(acc[mt][nt], ah[mt], bl);
                    mma8(acc[mt][nt], al[mt], bh);
                }
            }
        }
    }

    // attention scalar: per-row dot of relu(hidden + add) with w2
#pragma unroll
    for (int mt = 0; mt < 2; mt++) {
        int r0 = wr0 + mt * 16 + g, r1 = r0 + 8;
        const float2* ar0 = (const float2*)(addvec + (size_t)ia_s[r0] * HH);
        const float2* ar1 = (const float2*)(addvec + (size_t)ia_s[r1] * HH);
        float p0 = 0.f, p1 = 0.f;
#pragma unroll
        for (int nt = 0; nt < 8; nt++) {
            int c = wc0 + nt * 8 + t * 2;
            float w0 = w2_s[c], w1 = w2_s[c+1];
            float2 a0 = ar0[c >> 1], a1 = ar1[c >> 1];
            p0 += fmaxf(acc[mt][nt][0] + a0.x, 0.f) * w0
                + fmaxf(acc[mt][nt][1] + a0.y, 0.f) * w1;
            p1 += fmaxf(acc[mt][nt][2] + a1.x, 0.f) * w0
                + fmaxf(acc[mt][nt][3] + a1.y, 0.f) * w1;
        }
        p0 += __shfl_xor_sync(0xffffffffu, p0, 1);
        p0 += __shfl_xor_sync(0xffffffffu, p0, 2);
        p1 += __shfl_xor_sync(0xffffffffu, p1, 1);
        p1 += __shfl_xor_sync(0xffffffffu, p1, 2);
        if (t == 0) {
            part_s[r0 * 2 + (w & 1)] = p0;
            part_s[r1 * 2 + (w & 1)] = p1;
        }
    }
    __syncthreads();
    if (tid < 128) {
        float ps = part_s[tid * 2] + part_s[tid * 2 + 1];
        a_s[tid] = 1.f / (1.f + expf(-ps));
    }
    __syncthreads();

    // output epilogue: 128 rows x 32 float4 = 4096 float4 -> 16 iters of 256 threads
#pragma unroll
    for (int i = 0; i < 16; i++) {
        int f = tid + 256 * i;
        int r = f >> 5, q = (f & 31) << 2;
        size_t base = (size_t)(e0 + r) * HH + q;
        float4 iv = *(const float4*)(ie + base);
        float a = a_s[r];
        float4 o;
        if (mode == 0) {
            o = make_float4(iv.x*a, iv.y*a, iv.z*a, iv.w*a);
        } else {
            float4 v4 = *(const float4*)(V + (size_t)is_s[r] * HH + q);
            o.x = fmaxf(iv.x + a*v4.x, 0.f); o.y = fmaxf(iv.y + a*v4.y, 0.f);
            o.z = fmaxf(iv.z + a*v4.z, 0.f); o.w = fmaxf(iv.w + a*v4.w, 0.f);
        }
        *(float4*)(outp + base) = o;
    }
}

__global__ void k_zero(float* p, int n4) {
    int t = blockIdx.x*256 + threadIdx.x;
    if (t < n4) *(float4*)(p + (size_t)t*4) = make_float4(0.f,0.f,0.f,0.f);
}

__global__ void k_scatter(const float* __restrict__ me, const void* dstp) {
    int t = blockIdx.x*256 + threadIdx.x;
    int e = t >> 5, j4 = (t & 31) << 2;
    int dd = ld_idx(dstp, e, 0);
    float4 v = *(const float4*)(me + (size_t)e*HH + j4);
    float* a = g_agg + (size_t)dd*HH + j4;
    atomicAdd(a+0, v.x); atomicAdd(a+1, v.y);
    atomicAdd(a+2, v.z); atomicAdd(a+3, v.w);
}

__global__ void k_add2(const float* a, const float* b, float* o, int n) {
    int t = blockIdx.x*256 + threadIdx.x;
    if (t < n) o[t] = a[t] + b[t];
}

__global__ void k_concat3() {
    int t = blockIdx.x*256 + threadIdx.x;
    int r = t / 384, j = t % 384;
    float v;
    if (j < 128)      v = g_agg[(size_t)r*128 + j];
    else if (j < 256) v = g_mn[(size_t)r*128 + j - 128];
    else              v = g_in[(size_t)r*128 + j - 256];
    g_scratch[t] = v;
}

__global__ void k_msg(const float* __restrict__ gru_bias) {
    int t = blockIdx.x*256 + threadIdx.x;
    g_msg[t] = fmaxf(g_nodeh[t] + gru_bias[t & 127], 0.f);
}

__global__ void k_h0() {
    int b = blockIdx.x, j = threadIdx.x;
    float m = -1e30f;
    for (int s = 0; s < SS; s++)
        m = fmaxf(m, g_nodeh[((size_t)(b*SS + s))*HH + j]);
    g_h0[b*HH + j] = m;
}

__global__ void k_twih(const float* __restrict__ Wih) {
    int t = blockIdx.x*256 + threadIdx.x;
    if (t < 2*384*128) {
        int d = t / (384*128), rem = t % (384*128);
        int o = rem / 128, k = rem % 128;
        g_WihT[d*384*128 + k*384 + o] = Wih[t];
    }
}

__global__ void __launch_bounds__(384) k_gru(const float* __restrict__ Whh,
                                             const float* __restrict__ bhh)
{
    const int b = blockIdx.x, dir = blockIdx.y;
    const int o = threadIdx.x;
    float w[128];
    const float* wr = Whh + ((size_t)dir*384 + o)*128;
#pragma unroll
    for (int k = 0; k < 128; k += 4) {
        float4 v = *(const float4*)(wr + k);
        w[k]=v.x; w[k+1]=v.y; w[k+2]=v.z; w[k+3]=v.w;
    }
    const float bh = bhh[dir*384 + o];
    __shared__ float h_s[128];
    __shared__ float gh_s[384];
    if (o < 128) h_s[o] = g_h0[b*128 + o];
    __syncthreads();
    const float* gi = g_gi + (size_t)dir*NN*384;
    const int nsteps = (dir == 0) ? 2 : SS;
    for (int i2 = 0; i2 < nsteps; i2++) {
        int t = (dir == 0) ? i2 : (SS - 1 - i2);
        float gh = bh;
#pragma unroll
        for (int k = 0; k < 128; k += 4) {
            float4 hv = *(const float4*)&h_s[k];
            gh += w[k]*hv.x + w[k+1]*hv.y + w[k+2]*hv.z + w[k+3]*hv.w;
        }
        gh_s[o] = gh;
        __syncthreads();
        if (o < 128) {
            size_t gb = ((size_t)(b*SS + t))*384;
            float ir = gi[gb+o], iz = gi[gb+128+o], inn = gi[gb+256+o];
            float r = 1.f/(1.f+expf(-(ir + gh_s[o])));
            float z = 1.f/(1.f+expf(-(iz + gh_s[128+o])));
            float n = tanhf(inn + r*gh_s[256+o]);
            float hnew = (1.f-z)*n + z*h_s[o];
            if (dir == 0) {
                if (i2 == 0)      g_y[0*BB*128 + b*128 + o] = hnew;
                else if (i2 == 1) g_y[1*BB*128 + b*128 + o] = hnew;
            } else {
                if (i2 == SS-1)      g_y[2*BB*128 + b*128 + o] = hnew;
                else if (i2 == SS-2) g_y[3*BB*128 + b*128 + o] = hnew;
            }
            h_s[o] = hnew;
        }
        __syncthreads();
    }
}

__global__ void k_final(const float* __restrict__ Wo, const float* __restrict__ bo,
                        const float* __restrict__ rel_emb, const void* trg,
                        const float* __restrict__ l1W, const float* __restrict__ l1b,
                        const float* __restrict__ l2W, const float* __restrict__ l2b,
                        float* __restrict__ out)
{
    const int b = blockIdx.x, j = threadIdx.x;
    __shared__ float conv[128];
    __shared__ float s16[16];
    float hh = bo[j], ht = bo[j];
    const float* yf0 = g_y + 0*BB*128 + b*128;
    const float* yf1 = g_y + 1*BB*128 + b*128;
    const float* yb0 = g_y + 2*BB*128 + b*128;
    const float* yb1 = g_y + 3*BB*128 + b*128;
    for (int k = 0; k < 128; k++) {
        float wk = Wo[k*128 + j];
        hh += yf0[k]*wk; ht += yf1[k]*wk;
    }
    for (int k = 0; k < 128; k++) {
        float wk = Wo[(128+k)*128 + j];
        hh += yb0[k]*wk; ht += yb1[k]*wk;
    }
    hh = fmaxf(hh, 0.f); ht = fmaxf(ht, 0.f);
    int tr = ld_idx(trg, b, 1);
    conv[j] = tanhf(hh + rel_emb[tr*128 + j] - ht);
    __syncthreads();
    if (j < 16) {
        float s = l1b[j];
        for (int k = 0; k < 128; k++) s += conv[k]*l1W[k*16 + j];
        s16[j] = s;
    }
    __syncthreads();
    if (j == 0) {
        float o = l2b[0];
        for (int i = 0; i < 16; i++) o += s16[i]*l2W[i];
        out[b] = o;
    }
}

extern "C" void kernel_launch(void* const* d_in, const int* in_sizes, int n_in,
                              void* d_out, int out_size)
{
    const float* node_feat = (const float*)d_in[0];
    const float* rel_emb   = (const float*)d_in[1];
    const float* W_i_node  = (const float*)d_in[2];
    const float* W_i_edge  = (const float*)d_in[3];
    const float* W_att_in1 = (const float*)d_in[4];
    const float* W_att_in2 = (const float*)d_in[5];
    const float* W_h_node  = (const float*)d_in[6];
    const float* W_h_edge  = (const float*)d_in[7];
    const float* W_att1    = (const float*)d_in[8];
    const float* W_att2    = (const float*)d_in[9];
    const float* comm_W    = (const float*)d_in[10];
    const float* W_o       = (const float*)d_in[11];
    const float* b_o       = (const float*)d_in[12];
    const float* gru_bias  = (const float*)d_in[13];
    const float* gru_Wih   = (const float*)d_in[14];
    const float* gru_Whh   = (const float*)d_in[15];
    const float* gru_bih   = (const float*)d_in[16];
    const float* gru_bhh   = (const float*)d_in[17];
    const float* lin1_W    = (const float*)d_in[18];
    const float* lin1_b    = (const float*)d_in[19];
    const float* lin2_W    = (const float*)d_in[20];
    const float* lin2_b    = (const float*)d_in[21];
    const void*  src       = d_in[22];
    const void*  dst       = d_in[23];
    const void*  etype     = d_in[24];
    const void*  elabel    = d_in[25];
    const void*  trg       = d_in[26];
    float* out = (float*)d_out;

    float *ge_ie, *ge_me, *ge_in, *ge_P, *ge_D, *ge_U, *ge_mn, *ge_agg, *ge_V;
    float *ge_nodeh, *ge_msg, *ge_scr, *ge_gi, *ge_WihT, *ge_Qrel, *ge_Qd;
    cudaGetSymbolAddress((void**)&ge_ie, g_ie);
    cudaGetSymbolAddress((void**)&ge_me, g_me);
    cudaGetSymbolAddress((void**)&ge_in, g_in);
    cudaGetSymbolAddress((void**)&ge_P, g_P);
    cudaGetSymbolAddress((void**)&ge_D, g_D);
    cudaGetSymbolAddress((void**)&ge_U, g_U);
    cudaGetSymbolAddress((void**)&ge_mn, g_mn);
    cudaGetSymbolAddress((void**)&ge_agg, g_agg);
    cudaGetSymbolAddress((void**)&ge_V, g_V);
    cudaGetSymbolAddress((void**)&ge_nodeh, g_nodeh);
    cudaGetSymbolAddress((void**)&ge_msg, g_msg);
    cudaGetSymbolAddress((void**)&ge_scr, g_scratch);
    cudaGetSymbolAddress((void**)&ge_gi, g_gi);
    cudaGetSymbolAddress((void**)&ge_WihT, g_WihT);
    cudaGetSymbolAddress((void**)&ge_Qrel, g_Qrel);
    cudaGetSymbolAddress((void**)&ge_Qd, g_Qd);

    cudaFuncSetAttribute(k_tgemm, cudaFuncAttributeMaxDynamicSharedMemorySize, SM_BYTES);
    cudaFuncSetAttribute(k_edge_att_tc, cudaFuncAttributeMaxDynamicSharedMemorySize, SM_BYTES);

    k_detect<<<1, 32>>>(src, etype);

    // node-side GEMMs (tensor cores, 3xTF32)
    k_tgemm<<<dim3(NN/128, 1), 256, SM_BYTES>>>(node_feat, W_i_edge,           ge_P, 64, 128, NULL, 0);
    k_tgemm<<<dim3(NN/128, 1), 256, SM_BYTES>>>(node_feat, W_i_edge + 192*128, ge_D, 64, 128, NULL, 0);
    k_tgemm<<<dim3(NN/128, 1), 256, SM_BYTES>>>(node_feat, W_i_node,           ge_in, 64, 128, NULL, 1);
    // small rel_emb GEMMs (rows=32, SIMT)
    k_sgemm<<<dim3(1,2), 256>>>(rel_emb, W_i_edge + 64*128,         ge_Qrel,        RR, 128, 128, NULL, 0);
    k_sgemm<<<dim3(1,2), 256>>>(rel_emb, W_att1 + 128*128,          ge_Qd,          RR, 128, 128, NULL, 0);
    k_sgemm<<<dim3(1,2), 256>>>(rel_emb, W_att1 + 32768 + 128*128,  ge_Qd + RR*128, RR, 128, 128, NULL, 0);

    k_edge_init<<<NE*32/256, 256>>>(src, dst, etype);

    // input attention
    k_tgemm<<<dim3(NN/128, 1), 256, SM_BYTES>>>(ge_in, W_att_in1, ge_U, 128, 128, NULL, 0);
    k_edge_att_tc<<<NE/128, 256, SM_BYTES>>>(ge_ie, W_att_in1 + 128*128, ge_U, src, 0, src,
                                             W_att_in2, ge_ie, NULL, ge_me, 0);

    // two message-passing depths
    for (int d = 0; d < 2; d++) {
        const float* mn_old = (d == 0) ? ge_in : ge_mn;
        k_zero<<<NN*128/4/256, 256>>>(ge_agg, NN*128/4);
        k_scatter<<<NE*32/256, 256>>>(ge_me, dst);
        k_add2<<<NN*128/256, 256>>>(mn_old, ge_agg, ge_scr, NN*128);
        k_tgemm<<<dim3(NN/128, 1), 256, SM_BYTES>>>(ge_scr, W_h_node + d*16384, ge_mn, 128, 128, NULL, 1);
        k_tgemm<<<dim3(NN/128, 1), 256, SM_BYTES>>>(ge_mn, W_h_edge + d*16384, ge_V, 128, 128, NULL, 0);
        k_edge_att_tc<<<NE/128, 256, SM_BYTES>>>(ge_me, W_att1 + d*32768, ge_Qd + d*RR*128, elabel, 1,
                                                 src, W_att2 + d*128, ge_ie, ge_V, ge_me, 1);
    }

    // readout aggregation + comm
    k_zero<<<NN*128/4/256, 256>>>(ge_agg, NN*128/4);
    k_scatter<<<NE*32/256, 256>>>(ge_me, dst);
    k_concat3<<<NN*384/256, 256>>>();
    k_tgemm<<<dim3(NN/128, 1), 256, SM_BYTES>>>(ge_scr, comm_W, ge_nodeh, 384, 128, NULL, 0);

    // GRU
    k_msg<<<NN*128/256, 256>>>(gru_bias);
    k_h0<<<BB, 128>>>();
    k_twih<<<(2*384*128 + 255)/256, 256>>>(gru_Wih);
    k_tgemm<<<dim3(NN/128, 3), 256, SM_BYTES>>>(ge_msg, ge_WihT,           ge_gi,                  128, 384, gru_bih,       0);
    k_tgemm<<<dim3(NN/128, 3), 256, SM_BYTES>>>(ge_msg, ge_WihT + 384*128, ge_gi + (size_t)NN*384, 128, 384, gru_bih + 384, 0);
    k_gru<<<dim3(BB, 2), 384>>>(gru_Whh, gru_bhh);

    k_final<<<BB, 128>>>(W_o, b_o, rel_emb, trg, lin1_W, lin1_b, lin2_W, lin2_b, out);
}

// round 6
// speedup vs baseline: 1.4548x; 1.1427x over previous
#include <cuda_runtime.h>
#include <cuda_bf16.h>
#include <math.h>

#define NN 16384
#define NE 262144
#define HH 128
#define BB 64
#define SS 256
#define RR 32

__device__ float g_ie[NE*HH];
__device__ float g_me[NE*HH];
__device__ float g_in[NN*HH];
__device__ float g_P[NN*HH];
__device__ float g_D[NN*HH];
__device__ float g_U[NN*HH];
__device__ float g_mn[NN*HH];
__device__ float g_agg[NN*HH];
__device__ float g_V[NN*HH];
__device__ float g_nodeh[NN*HH];
__device__ float g_msg[NN*HH];
__device__ float g_scr[NN*HH];
__device__ float g_gi[NN*384];        // backward dir only
__device__ float g_gif[128*384];      // forward dir, head/tail rows only
__device__ float g_msg2[128*HH];
__device__ float g_WihT[2*384*128];
__device__ float g_Qrel[RR*HH];
__device__ float g_Qd[2*RR*HH];
__device__ float g_h0[BB*HH];
__device__ float g_y[4*BB*HH];
__device__ int   g_is64[2];
__device__ int   g_cnt[NN];
__device__ int   g_off[NN+1];
__device__ int   g_cur[NN];
__device__ int   g_eid[NE];

__device__ __forceinline__ int ld_idx(const void* p, long long i, int sel) {
    if (g_is64[sel]) return (int)((const long long*)p)[i];
    return ((const int*)p)[i];
}

__global__ void k_detect(const void* src, const void* et) {
    if (threadIdx.x == 0) {
        const unsigned long long* a = (const unsigned long long*)src;
        int v = 1;
        for (int i = 0; i < 8; i++) if (a[i] >= (unsigned long long)NN) v = 0;
        g_is64[0] = v;
        const unsigned long long* b = (const unsigned long long*)et;
        v = 1;
        for (int i = 0; i < 8; i++) if (b[i] >= (unsigned long long)RR) v = 0;
        g_is64[1] = v;
    }
}

// ---------- bf16 hi/lo helpers ----------
__device__ __forceinline__ void f2bf(float x, unsigned short& h, unsigned short& l) {
    __nv_bfloat16 bh = __float2bfloat16(x);
    h = __bfloat16_as_ushort(bh);
    l = __bfloat16_as_ushort(__float2bfloat16(x - __bfloat162float(bh)));
}

__device__ __forceinline__ void mma16(float* d, const unsigned* a, const unsigned* b) {
    asm volatile("mma.sync.aligned.m16n8k16.row.col.f32.bf16.bf16.f32 "
        "{%0,%1,%2,%3}, {%4,%5,%6,%7}, {%8,%9}, {%0,%1,%2,%3};"
        : "+f"(d[0]), "+f"(d[1]), "+f"(d[2]), "+f"(d[3])
        : "r"(a[0]), "r"(a[1]), "r"(a[2]), "r"(a[3]), "r"(b[0]), "r"(b[1]));
}

#define APITCH 40
#define WPITCH 42

// ---------- bf16 3-split tensor-core GEMM ----------
// C[rows,M] = act(A[rows,K]@W[K,M] + bias [+ Cold]); rows%128==0, K%32==0, M%128==0
__global__ void __launch_bounds__(256) k_tgemm_bf(
    const float* __restrict__ A, const float* __restrict__ W, float* __restrict__ C,
    int K, int M, const float* __restrict__ bias, int doRelu, int accum)
{
    __shared__ unsigned short sAh[128*APITCH], sAl[128*APITCH];
    __shared__ unsigned short sWh[128*WPITCH], sWl[128*WPITCH];
    const int tid = threadIdx.x;
    const int w = tid >> 5, lane = tid & 31;
    const int g = lane >> 2, t = lane & 3;
    const int wr0 = (w >> 1) * 32, wc0 = (w & 1) * 64;
    const long long row0 = (long long)blockIdx.x * 128;
    const int col0 = blockIdx.y * 128;

    float acc[2][8][4];
#pragma unroll
    for (int a = 0; a < 2; a++)
#pragma unroll
        for (int b = 0; b < 8; b++)
#pragma unroll
            for (int c = 0; c < 4; c++) acc[a][b][c] = 0.f;

    for (int k0 = 0; k0 < K; k0 += 32) {
        __syncthreads();
#pragma unroll
        for (int i = 0; i < 4; i++) {
            int f = tid + 256 * i;
            int r = f >> 3, j = (f & 7) << 2;
            float4 v = *(const float4*)(A + (row0 + r) * K + k0 + j);
            unsigned short h, l;
            f2bf(v.x, h, l); sAh[r*APITCH+j+0] = h; sAl[r*APITCH+j+0] = l;
            f2bf(v.y, h, l); sAh[r*APITCH+j+1] = h; sAl[r*APITCH+j+1] = l;
            f2bf(v.z, h, l); sAh[r*APITCH+j+2] = h; sAl[r*APITCH+j+2] = l;
            f2bf(v.w, h, l); sAh[r*APITCH+j+3] = h; sAl[r*APITCH+j+3] = l;
        }
#pragma unroll
        for (int i = 0; i < 4; i++) {
            int f = tid + 256 * i;
            int kk = f >> 5, c = (f & 31) << 2;
            float4 v = *(const float4*)(W + (long long)(k0 + kk) * M + col0 + c);
            unsigned short h, l;
            f2bf(v.x, h, l); sWh[(c+0)*WPITCH+kk] = h; sWl[(c+0)*WPITCH+kk] = l;
            f2bf(v.y, h, l); sWh[(c+1)*WPITCH+kk] = h; sWl[(c+1)*WPITCH+kk] = l;
            f2bf(v.z, h, l); sWh[(c+2)*WPITCH+kk] = h; sWl[(c+2)*WPITCH+kk] = l;
            f2bf(v.w, h, l); sWh[(c+3)*WPITCH+kk] = h; sWl[(c+3)*WPITCH+kk] = l;
        }
        __syncthreads();
#pragma unroll
        for (int ks = 0; ks < 32; ks += 16) {
            unsigned ah[2][4], al[2][4];
#pragma unroll
            for (int mt = 0; mt < 2; mt++) {
                int rb = wr0 + mt * 16 + g;
                const unsigned short* p = &sAh[rb*APITCH + ks + 2*t];
                ah[mt][0] = *(const unsigned*)p;
                ah[mt][1] = *(const unsigned*)(p + 8*APITCH);
                ah[mt][2] = *(const unsigned*)(p + 8);
                ah[mt][3] = *(const unsigned*)(p + 8*APITCH + 8);
                const unsigned short* q = &sAl[rb*APITCH + ks + 2*t];
                al[mt][0] = *(const unsigned*)q;
                al[mt][1] = *(const unsigned*)(q + 8*APITCH);
                al[mt][2] = *(const unsigned*)(q + 8);
                al[mt][3] = *(const unsigned*)(q + 8*APITCH + 8);
            }
#pragma unroll
            for (int nt = 0; nt < 8; nt++) {
                int cn = wc0 + nt * 8 + g;
                unsigned bh[2], bl[2];
                const unsigned short* p = &sWh[cn*WPITCH + ks + 2*t];
                bh[0] = *(const unsigned*)p; bh[1] = *(const unsigned*)(p + 8);
                const unsigned short* q = &sWl[cn*WPITCH + ks + 2*t];
                bl[0] = *(const unsigned*)q; bl[1] = *(const unsigned*)(q + 8);
#pragma unroll
                for (int mt = 0; mt < 2; mt++) {
                    mma16(acc[mt][nt], ah[mt], bh);
                    mma16(acc[mt][nt], ah[mt], bl);
                    mma16(acc[mt][nt], al[mt], bh);
                }
            }
        }
    }
#pragma unroll
    for (int mt = 0; mt < 2; mt++) {
#pragma unroll
        for (int nt = 0; nt < 8; nt++) {
            int c = col0 + wc0 + nt * 8 + t * 2;
            long long r0 = row0 + wr0 + mt * 16 + g;
            float b0 = bias ? bias[c] : 0.f, b1 = bias ? bias[c+1] : 0.f;
            float v0 = acc[mt][nt][0] + b0, v1 = acc[mt][nt][1] + b1;
            float v2 = acc[mt][nt][2] + b0, v3 = acc[mt][nt][3] + b1;
            if (accum) {
                float2 o0 = *(const float2*)(C + r0 * M + c);
                float2 o1 = *(const float2*)(C + (r0 + 8) * M + c);
                v0 += o0.x; v1 += o0.y; v2 += o1.x; v3 += o1.y;
            }
            if (doRelu) {
                v0 = fmaxf(v0, 0.f); v1 = fmaxf(v1, 0.f);
                v2 = fmaxf(v2, 0.f); v3 = fmaxf(v3, 0.f);
            }
            *(float2*)(C + r0 * M + c)       = make_float2(v0, v1);
            *(float2*)(C + (r0 + 8) * M + c) = make_float2(v2, v3);
        }
    }
}

// ---------- small SIMT GEMM for 32-row rel_emb GEMMs ----------
__global__ void k_sgemm(const float* __restrict__ A, const float* __restrict__ W,
                        float* __restrict__ C, int rows, int K, int M)
{
    __shared__ float As[16][64];
    __shared__ float Ws[16][64];
    const int tid = threadIdx.x;
    const int tx = tid & 15, ty = tid >> 4;
    const int row0 = blockIdx.x * 64, col0 = blockIdx.y * 64;
    const int la_r = tid >> 2, la_k = (tid & 3) << 2;
    const int lw_k = tid >> 4, lw_c = (tid & 15) << 2;
    float acc[4][4];
#pragma unroll
    for (int i = 0; i < 4; i++)
#pragma unroll
        for (int j = 0; j < 4; j++) acc[i][j] = 0.f;
    for (int k0 = 0; k0 < K; k0 += 16) {
        float4 av = make_float4(0.f,0.f,0.f,0.f);
        if (row0 + la_r < rows)
            av = *(const float4*)(A + (size_t)(row0 + la_r) * K + (k0 + la_k));
        As[la_k+0][la_r] = av.x; As[la_k+1][la_r] = av.y;
        As[la_k+2][la_r] = av.z; As[la_k+3][la_r] = av.w;
        *(float4*)&Ws[lw_k][lw_c] = *(const float4*)(W + (size_t)(k0+lw_k)*M + col0 + lw_c);
        __syncthreads();
#pragma unroll
        for (int k = 0; k < 16; k++) {
            float4 a4 = *(const float4*)&As[k][ty<<2];
            float4 w4 = *(const float4*)&Ws[k][tx<<2];
            float ar[4] = {a4.x,a4.y,a4.z,a4.w};
            float wr[4] = {w4.x,w4.y,w4.z,w4.w};
#pragma unroll
            for (int i = 0; i < 4; i++)
#pragma unroll
                for (int j = 0; j < 4; j++) acc[i][j] += ar[i]*wr[j];
        }
        __syncthreads();
    }
#pragma unroll
    for (int i = 0; i < 4; i++) {
        int r = row0 + (ty<<2) + i;
        if (r < rows)
#pragma unroll
            for (int j = 0; j < 4; j++)
                C[(size_t)r*M + col0 + (tx<<2) + j] = acc[i][j];
    }
}

__global__ void k_edge_init(const void* srcp, const void* dstp, const void* etp) {
    int t = blockIdx.x*256 + threadIdx.x;
    int e = t >> 5, j4 = (t & 31) << 2;
    int s = ld_idx(srcp,e,0), dd = ld_idx(dstp,e,0), et = ld_idx(etp,e,1);
    float4 p = *(const float4*)(g_P + (size_t)s*HH + j4);
    float4 q = *(const float4*)(g_Qrel + (size_t)et*HH + j4);
    float4 d = *(const float4*)(g_D + (size_t)dd*HH + j4);
    float4 o;
    o.x = fmaxf(p.x+q.x+d.x, 0.f); o.y = fmaxf(p.y+q.y+d.y, 0.f);
    o.z = fmaxf(p.z+q.z+d.z, 0.f); o.w = fmaxf(p.w+q.w+d.w, 0.f);
    *(float4*)(g_ie + (size_t)e*HH + j4) = o;
}

// ---------- bf16 tensor-core fused edge attention ----------
__global__ void __launch_bounds__(256) k_edge_att_tc(
    const float* __restrict__ X, const float* __restrict__ Wm,
    const float* __restrict__ addvec, const void* idx_add, int sel_add,
    const void* idx_src, const float* __restrict__ w2,
    const float* __restrict__ ie, const float* __restrict__ V,
    float* __restrict__ outp, int mode)
{
    __shared__ unsigned short sAh[128*APITCH], sAl[128*APITCH];
    __shared__ unsigned short sWh[128*WPITCH], sWl[128*WPITCH];
    __shared__ int ia_s[128], is_s[128];
    __shared__ float a_s[128], part_s[256], w2_s[128];

    const int tid = threadIdx.x;
    const int w = tid >> 5, lane = tid & 31;
    const int g = lane >> 2, t = lane & 3;
    const int wr0 = (w >> 1) * 32, wc0 = (w & 1) * 64;
    const long long e0 = (long long)blockIdx.x * 128;

    if (tid < 128) {
        ia_s[tid] = ld_idx(idx_add, e0 + tid, sel_add);
        is_s[tid] = ld_idx(idx_src, e0 + tid, 0);
        w2_s[tid] = w2[tid];
    }

    float acc[2][8][4];
#pragma unroll
    for (int a = 0; a < 2; a++)
#pragma unroll
        for (int b = 0; b < 8; b++)
#pragma unroll
            for (int c = 0; c < 4; c++) acc[a][b][c] = 0.f;

    for (int k0 = 0; k0 < 128; k0 += 32) {
        __syncthreads();
#pragma unroll
        for (int i = 0; i < 4; i++) {
            int f = tid + 256 * i;
            int r = f >> 3, j = (f & 7) << 2;
            float4 v = *(const float4*)(X + (e0 + r) * HH + k0 + j);
            unsigned short h, l;
            f2bf(v.x, h, l); sAh[r*APITCH+j+0] = h; sAl[r*APITCH+j+0] = l;
            f2bf(v.y, h, l); sAh[r*APITCH+j+1] = h; sAl[r*APITCH+j+1] = l;
            f2bf(v.z, h, l); sAh[r*APITCH+j+2] = h; sAl[r*APITCH+j+2] = l;
            f2bf(v.w, h, l); sAh[r*APITCH+j+3] = h; sAl[r*APITCH+j+3] = l;
        }
#pragma unroll
        for (int i = 0; i < 4; i++) {
            int f = tid + 256 * i;
            int kk = f >> 5, c = (f & 31) << 2;
            float4 v = *(const float4*)(Wm + (long long)(k0 + kk) * HH + c);
            unsigned short h, l;
            f2bf(v.x, h, l); sWh[(c+0)*WPITCH+kk] = h; sWl[(c+0)*WPITCH+kk] = l;
            f2bf(v.y, h, l); sWh[(c+1)*WPITCH+kk] = h; sWl[(c+1)*WPITCH+kk] = l;
            f2bf(v.z, h, l); sWh[(c+2)*WPITCH+kk] = h; sWl[(c+2)*WPITCH+kk] = l;
            f2bf(v.w, h, l); sWh[(c+3)*WPITCH+kk] = h; sWl[(c+3)*WPITCH+kk] = l;
        }
        __syncthreads();
#pragma unroll
        for (int ks = 0; ks < 32; ks += 16) {
            unsigned ah[2][4], al[2][4];
#pragma unroll
            for (int mt = 0; mt < 2; mt++) {
                int rb = wr0 + mt * 16 + g;
                const unsigned short* p = &sAh[rb*APITCH + ks + 2*t];
                ah[mt][0] = *(const unsigned*)p;
                ah[mt][1] = *(const unsigned*)(p + 8*APITCH);
                ah[mt][2] = *(const unsigned*)(p + 8);
                ah[mt][3] = *(const unsigned*)(p + 8*APITCH + 8);
                const unsigned short* q = &sAl[rb*APITCH + ks + 2*t];
                al[mt][0] = *(const unsigned*)q;
                al[mt][1] = *(const unsigned*)(q + 8*APITCH);
                al[mt][2] = *(const unsigned*)(q + 8);
                al[mt][3] = *(const unsigned*)(q + 8*APITCH + 8);
            }
#pragma unroll
            for (int nt = 0; nt < 8; nt++) {
                int cn = wc0 + nt * 8 + g;
                unsigned bh[2], bl[2];
                const unsigned short* p = &sWh[cn*WPITCH + ks + 2*t];
                bh[0] = *(const unsigned*)p; bh[1] = *(const unsigned*)(p + 8);
                const unsigned short* q = &sWl[cn*WPITCH + ks + 2*t];
                bl[0] = *(const unsigned*)q; bl[1] = *(const unsigned*)(q + 8);
#pragma unroll
                for (int mt = 0; mt < 2; mt++) {
                    mma16(acc[mt][nt], ah[mt], bh);
                    mma16(acc[mt][nt], ah[mt], bl);
                    mma16(acc[mt][nt], al[mt], bh);
                }
            }
        }
    }

    // attention scalar: per-row dot of relu(hidden + add) with w2
#pragma unroll
    for (int mt = 0; mt < 2; mt++) {
        int r0 = wr0 + mt * 16 + g, r1 = r0 + 8;
        const float2* ar0 = (const float2*)(addvec + (size_t)ia_s[r0] * HH);
        const float2* ar1 = (const float2*)(addvec + (size_t)ia_s[r1] * HH);
        float p0 = 0.f, p1 = 0.f;
#pragma unroll
        for (int nt = 0; nt < 8; nt++) {
            int c = wc0 + nt * 8 + t * 2;
            float w0 = w2_s[c], w1 = w2_s[c+1];
            float2 a0 = ar0[c >> 1], a1 = ar1[c >> 1];
            p0 += fmaxf(acc[mt][nt][0] + a0.x, 0.f) * w0
                + fmaxf(acc[mt][nt][1] + a0.y, 0.f) * w1;
            p1 += fmaxf(acc[mt][nt][2] + a1.x, 0.f) * w0
                + fmaxf(acc[mt][nt][3] + a1.y, 0.f) * w1;
        }
        p0 += __shfl_xor_sync(0xffffffffu, p0, 1);
        p0 += __shfl_xor_sync(0xffffffffu, p0, 2);
        p1 += __shfl_xor_sync(0xffffffffu, p1, 1);
        p1 += __shfl_xor_sync(0xffffffffu, p1, 2);
        if (t == 0) {
            part_s[r0 * 2 + (w & 1)] = p0;
            part_s[r1 * 2 + (w & 1)] = p1;
        }
    }
    __syncthreads();
    if (tid < 128) {
        float ps = part_s[tid * 2] + part_s[tid * 2 + 1];
        a_s[tid] = 1.f / (1.f + expf(-ps));
    }
    __syncthreads();

    // output epilogue: 128 rows x 32 float4 = 4096 float4
#pragma unroll
    for (int i = 0; i < 16; i++) {
        int f = tid + 256 * i;
        int r = f >> 5, q = (f & 31) << 2;
        size_t base = (size_t)(e0 + r) * HH + q;
        float4 iv = *(const float4*)(ie + base);
        float a = a_s[r];
        float4 o;
        if (mode == 0) {
            o = make_float4(iv.x*a, iv.y*a, iv.z*a, iv.w*a);
        } else {
            float4 v4 = *(const float4*)(V + (size_t)is_s[r] * HH + q);
            o.x = fmaxf(iv.x + a*v4.x, 0.f); o.y = fmaxf(iv.y + a*v4.y, 0.f);
            o.z = fmaxf(iv.z + a*v4.z, 0.f); o.w = fmaxf(iv.w + a*v4.w, 0.f);
        }
        *(float4*)(outp + base) = o;
    }
}

// ---------- CSR build ----------
__global__ void k_cnt_zero() {
    int t = blockIdx.x*256 + threadIdx.x;
    if (t < NN) g_cnt[t] = 0;
}
__global__ void k_count(const void* dstp) {
    int e = blockIdx.x*256 + threadIdx.x;
    if (e < NE) atomicAdd(&g_cnt[ld_idx(dstp, e, 0)], 1);
}
__global__ void __launch_bounds__(1024) k_scan() {
    __shared__ int ps[1024];
    int t = threadIdx.x;
    int base = t * 16;
    int loc[16];
    int s = 0;
#pragma unroll
    for (int i = 0; i < 16; i++) { loc[i] = g_cnt[base + i]; s += loc[i]; }
    ps[t] = s;
    __syncthreads();
    for (int off = 1; off < 1024; off <<= 1) {
        int v = (t >= off) ? ps[t - off] : 0;
        __syncthreads();
        ps[t] += v;
        __syncthreads();
    }
    int run = ps[t] - s;   // exclusive
#pragma unroll
    for (int i = 0; i < 16; i++) {
        g_off[base + i] = run;
        g_cur[base + i] = run;
        run += loc[i];
    }
    if (t == 1023) g_off[NN] = run;
}
__global__ void k_fill(const void* dstp) {
    int e = blockIdx.x*256 + threadIdx.x;
    if (e < NE) {
        int d = ld_idx(dstp, e, 0);
        int pos = atomicAdd(&g_cur[d], 1);
        g_eid[pos] = e;
    }
}

// ---------- CSR gather aggregation: out[n] = (add?add[n]:0) + sum_{e: dst=n} me[e] ----------
__global__ void __launch_bounds__(128) k_gather(const float* __restrict__ me,
                                                const float* __restrict__ addb,
                                                float* __restrict__ out)
{
    int n = blockIdx.x, j = threadIdx.x;
    int o0 = g_off[n], o1 = g_off[n+1];
    float s = addb ? addb[(size_t)n*HH + j] : 0.f;
    for (int i = o0; i < o1; i++) {
        int e = g_eid[i];
        s += me[(size_t)e*HH + j];
    }
    out[(size_t)n*HH + j] = s;
}

// ---------- GRU prep ----------
__global__ void k_msg(const float* __restrict__ gru_bias) {
    int t = blockIdx.x*256 + threadIdx.x;
    g_msg[t] = fmaxf(g_nodeh[t] + gru_bias[t & 127], 0.f);
}
__global__ void k_h0() {
    int b = blockIdx.x, j = threadIdx.x;
    float m = -1e30f;
    for (int s = 0; s < SS; s++)
        m = fmaxf(m, g_nodeh[((size_t)(b*SS + s))*HH + j]);
    g_h0[b*HH + j] = m;
}
__global__ void k_twih(const float* __restrict__ Wih) {
    int t = blockIdx.x*256 + threadIdx.x;
    if (t < 2*384*128) {
        int d = t / (384*128), rem = t % (384*128);
        int o = rem / 128, k = rem % 128;
        g_WihT[d*384*128 + k*384 + o] = Wih[t];
    }
}
__global__ void k_msg2() {
    int t = blockIdx.x*256 + threadIdx.x;   // 128*128
    int r = t >> 7, j = t & 127;
    int b = r >> 1, s = r & 1;
    g_msg2[t] = g_msg[((size_t)(b*SS + s))*HH + j];
}

__global__ void __launch_bounds__(384) k_gru(const float* __restrict__ Whh,
                                             const float* __restrict__ bhh)
{
    const int b = blockIdx.x, dir = blockIdx.y;
    const int o = threadIdx.x;
    float w[128];
    const float* wr = Whh + ((size_t)dir*384 + o)*128;
#pragma unroll
    for (int k = 0; k < 128; k += 4) {
        float4 v = *(const float4*)(wr + k);
        w[k]=v.x; w[k+1]=v.y; w[k+2]=v.z; w[k+3]=v.w;
    }
    const float bh = bhh[dir*384 + o];
    __shared__ float h_s[128];
    __shared__ float gh_s[384];
    if (o < 128) h_s[o] = g_h0[b*128 + o];
    __syncthreads();
    const int nsteps = (dir == 0) ? 2 : SS;
    for (int i2 = 0; i2 < nsteps; i2++) {
        int t = (dir == 0) ? i2 : (SS - 1 - i2);
        float gh = bh;
#pragma unroll
        for (int k = 0; k < 128; k += 4) {
            float4 hv = *(const float4*)&h_s[k];
            gh += w[k]*hv.x + w[k+1]*hv.y + w[k+2]*hv.z + w[k+3]*hv.w;
        }
        gh_s[o] = gh;
        __syncthreads();
        if (o < 128) {
            const float* gi = (dir == 0) ? (g_gif + (size_t)(b*2 + t)*384)
                                         : (g_gi  + (size_t)(b*SS + t)*384);
            float ir = gi[o], iz = gi[128+o], inn = gi[256+o];
            float r = 1.f/(1.f+expf(-(ir + gh_s[o])));
            float z = 1.f/(1.f+expf(-(iz + gh_s[128+o])));
            float n = tanhf(inn + r*gh_s[256+o]);
            float hnew = (1.f-z)*n + z*h_s[o];
            if (dir == 0) {
                if (i2 == 0)      g_y[0*BB*128 + b*128 + o] = hnew;
                else if (i2 == 1) g_y[1*BB*128 + b*128 + o] = hnew;
            } else {
                if (i2 == SS-1)      g_y[2*BB*128 + b*128 + o] = hnew;
                else if (i2 == SS-2) g_y[3*BB*128 + b*128 + o] = hnew;
            }
            h_s[o] = hnew;
        }
        __syncthreads();
    }
}

__global__ void k_final(const float* __restrict__ Wo, const float* __restrict__ bo,
                        const float* __restrict__ rel_emb, const void* trg,
                        const float* __restrict__ l1W, const float* __restrict__ l1b,
                        const float* __restrict__ l2W, const float* __restrict__ l2b,
                        float* __restrict__ out)
{
    const int b = blockIdx.x, j = threadIdx.x;
    __shared__ float conv[128];
    __shared__ float s16[16];
    float hh = bo[j], ht = bo[j];
    const float* yf0 = g_y + 0*BB*128 + b*128;
    const float* yf1 = g_y + 1*BB*128 + b*128;
    const float* yb0 = g_y + 2*BB*128 + b*128;
    const float* yb1 = g_y + 3*BB*128 + b*128;
    for (int k = 0; k < 128; k++) {
        float wk = Wo[k*128 + j];
        hh += yf0[k]*wk; ht += yf1[k]*wk;
    }
    for (int k = 0; k < 128; k++) {
        float wk = Wo[(128+k)*128 + j];
        hh += yb0[k]*wk; ht += yb1[k]*wk;
    }
    hh = fmaxf(hh, 0.f); ht = fmaxf(ht, 0.f);
    int tr = ld_idx(trg, b, 1);
    conv[j] = tanhf(hh + rel_emb[tr*128 + j] - ht);
    __syncthreads();
    if (j < 16) {
        float s = l1b[j];
        for (int k = 0; k < 128; k++) s += conv[k]*l1W[k*16 + j];
        s16[j] = s;
    }
    __syncthreads();
    if (j == 0) {
        float o = l2b[0];
        for (int i = 0; i < 16; i++) o += s16[i]*l2W[i];
        out[b] = o;
    }
}

extern "C" void kernel_launch(void* const* d_in, const int* in_sizes, int n_in,
                              void* d_out, int out_size)
{
    const float* node_feat = (const float*)d_in[0];
    const float* rel_emb   = (const float*)d_in[1];
    const float* W_i_node  = (const float*)d_in[2];
    const float* W_i_edge  = (const float*)d_in[3];
    const float* W_att_in1 = (const float*)d_in[4];
    const float* W_att_in2 = (const float*)d_in[5];
    const float* W_h_node  = (const float*)d_in[6];
    const float* W_h_edge  = (const float*)d_in[7];
    const float* W_att1    = (const float*)d_in[8];
    const float* W_att2    = (const float*)d_in[9];
    const float* comm_W    = (const float*)d_in[10];
    const float* W_o       = (const float*)d_in[11];
    const float* b_o       = (const float*)d_in[12];
    const float* gru_bias  = (const float*)d_in[13];
    const float* gru_Wih   = (const float*)d_in[14];
    const float* gru_Whh   = (const float*)d_in[15];
    const float* gru_bih   = (const float*)d_in[16];
    const float* gru_bhh   = (const float*)d_in[17];
    const float* lin1_W    = (const float*)d_in[18];
    const float* lin1_b    = (const float*)d_in[19];
    const float* lin2_W    = (const float*)d_in[20];
    const float* lin2_b    = (const float*)d_in[21];
    const void*  src       = d_in[22];
    const void*  dst       = d_in[23];
    const void*  etype     = d_in[24];
    const void*  elabel    = d_in[25];
    const void*  trg       = d_in[26];
    float* out = (float*)d_out;

    float *ge_ie, *ge_me, *ge_in, *ge_P, *ge_D, *ge_U, *ge_mn, *ge_agg, *ge_V;
    float *ge_nodeh, *ge_msg, *ge_scr, *ge_gi, *ge_gif, *ge_msg2, *ge_WihT, *ge_Qrel, *ge_Qd;
    cudaGetSymbolAddress((void**)&ge_ie, g_ie);
    cudaGetSymbolAddress((void**)&ge_me, g_me);
    cudaGetSymbolAddress((void**)&ge_in, g_in);
    cudaGetSymbolAddress((void**)&ge_P, g_P);
    cudaGetSymbolAddress((void**)&ge_D, g_D);
    cudaGetSymbolAddress((void**)&ge_U, g_U);
    cudaGetSymbolAddress((void**)&ge_mn, g_mn);
    cudaGetSymbolAddress((void**)&ge_agg, g_agg);
    cudaGetSymbolAddress((void**)&ge_V, g_V);
    cudaGetSymbolAddress((void**)&ge_nodeh, g_nodeh);
    cudaGetSymbolAddress((void**)&ge_msg, g_msg);
    cudaGetSymbolAddress((void**)&ge_scr, g_scr);
    cudaGetSymbolAddress((void**)&ge_gi, g_gi);
    cudaGetSymbolAddress((void**)&ge_gif, g_gif);
    cudaGetSymbolAddress((void**)&ge_msg2, g_msg2);
    cudaGetSymbolAddress((void**)&ge_WihT, g_WihT);
    cudaGetSymbolAddress((void**)&ge_Qrel, g_Qrel);
    cudaGetSymbolAddress((void**)&ge_Qd, g_Qd);

    k_detect<<<1, 32>>>(src, etype);

    // CSR of dst (shared by all three aggregations)
    k_cnt_zero<<<NN/256, 256>>>();
    k_count<<<NE/256, 256>>>(dst);
    k_scan<<<1, 1024>>>();
    k_fill<<<NE/256, 256>>>(dst);

    // node-side GEMMs (bf16 3-split tensor cores)
    k_tgemm_bf<<<dim3(NN/128, 1), 256>>>(node_feat, W_i_edge,           ge_P, 64, 128, NULL, 0, 0);
    k_tgemm_bf<<<dim3(NN/128, 1), 256>>>(node_feat, W_i_edge + 192*128, ge_D, 64, 128, NULL, 0, 0);
    k_tgemm_bf<<<dim3(NN/128, 1), 256>>>(node_feat, W_i_node,           ge_in, 64, 128, NULL, 1, 0);
    // small rel_emb GEMMs (rows=32, SIMT fp32)
    k_sgemm<<<dim3(1,2), 256>>>(rel_emb, W_i_edge + 64*128,         ge_Qrel,        RR, 128, 128);
    k_sgemm<<<dim3(1,2), 256>>>(rel_emb, W_att1 + 128*128,          ge_Qd,          RR, 128, 128);
    k_sgemm<<<dim3(1,2), 256>>>(rel_emb, W_att1 + 32768 + 128*128,  ge_Qd + RR*128, RR, 128, 128);

    k_edge_init<<<NE*32/256, 256>>>(src, dst, etype);

    // input attention
    k_tgemm_bf<<<dim3(NN/128, 1), 256>>>(ge_in, W_att_in1, ge_U, 128, 128, NULL, 0, 0);
    k_edge_att_tc<<<NE/128, 256>>>(ge_ie, W_att_in1 + 128*128, ge_U, src, 0, src,
                                   W_att_in2, ge_ie, NULL, ge_me, 0);

    // two message-passing depths
    for (int d = 0; d < 2; d++) {
        const float* mn_old = (d == 0) ? ge_in : ge_mn;
        k_gather<<<NN, 128>>>(ge_me, mn_old, ge_scr);
        k_tgemm_bf<<<dim3(NN/128, 1), 256>>>(ge_scr, W_h_node + d*16384, ge_mn, 128, 128, NULL, 1, 0);
        k_tgemm_bf<<<dim3(NN/128, 1), 256>>>(ge_mn, W_h_edge + d*16384, ge_V, 128, 128, NULL, 0, 0);
        k_edge_att_tc<<<NE/128, 256>>>(ge_me, W_att1 + d*32768, ge_Qd + d*RR*128, elabel, 1,
                                       src, W_att2 + d*128, ge_ie, ge_V, ge_me, 1);
    }

    // readout aggregation + comm (3 accumulating K=128 GEMMs replace concat)
    k_gather<<<NN, 128>>>(ge_me, NULL, ge_agg);
    k_tgemm_bf<<<dim3(NN/128, 1), 256>>>(ge_agg, comm_W,           ge_nodeh, 128, 128, NULL, 0, 0);
    k_tgemm_bf<<<dim3(NN/128, 1), 256>>>(ge_mn,  comm_W + 128*128, ge_nodeh, 128, 128, NULL, 0, 1);
    k_tgemm_bf<<<dim3(NN/128, 1), 256>>>(ge_in,  comm_W + 256*128, ge_nodeh, 128, 128, NULL, 0, 1);

    // GRU
    k_msg<<<NN*128/256, 256>>>(gru_bias);
    k_h0<<<BB, 128>>>();
    k_twih<<<(2*384*128 + 255)/256, 256>>>(gru_Wih);
    k_msg2<<<128*128/256, 256>>>();
    k_tgemm_bf<<<dim3(1, 3), 256>>>(ge_msg2, ge_WihT,           ge_gif, 128, 384, gru_bih,       0, 0);
    k_tgemm_bf<<<dim3(NN/128, 3), 256>>>(ge_msg, ge_WihT + 384*128, ge_gi, 128, 384, gru_bih + 384, 0, 0);
    k_gru<<<dim3(BB, 2), 384>>>(gru_Whh, gru_bhh);

    k_final<<<BB, 128>>>(W_o, b_o, rel_emb, trg, lin1_W, lin1_b, lin2_W, lin2_b, out);
}

// round 7
// speedup vs baseline: 1.6373x; 1.1254x over previous
#include <cuda_runtime.h>
#include <cuda_bf16.h>
#include <math.h>

#define NN 16384
#define NE 262144
#define HH 128
#define BB 64
#define SS 256
#define RR 32

__device__ float g_ie[NE*HH];
__device__ float g_me[NE*HH];
__device__ float g_in[NN*HH];
__device__ float g_P[NN*HH];
__device__ float g_D[NN*HH];
__device__ float g_U[NN*HH];
__device__ float g_mn[NN*HH];
__device__ float g_agg[NN*HH];
__device__ float g_V[NN*HH];
__device__ float g_nodeh[NN*HH];
__device__ float g_msg[NN*HH];
__device__ float g_scr[NN*HH];
__device__ float g_gi[NN*384];
__device__ float g_gif[128*384];
__device__ float g_msg2[128*HH];
__device__ float g_WihT[2*384*128];
__device__ float g_Qrel[RR*HH];
__device__ float g_Qd[2*RR*HH];
__device__ float g_h0[BB*HH];
__device__ float g_y[4*BB*HH];
__device__ int   g_is64[2];
__device__ int   g_cnt[NN];
__device__ int   g_off[NN+1];
__device__ int   g_cur[NN];
__device__ int   g_eid[NE];

__device__ __forceinline__ int ld_idx(const void* p, long long i, int sel) {
    if (g_is64[sel]) return (int)((const long long*)p)[i];
    return ((const int*)p)[i];
}

__global__ void k_detect(const void* src, const void* et) {
    if (threadIdx.x == 0) {
        const unsigned long long* a = (const unsigned long long*)src;
        int v = 1;
        for (int i = 0; i < 8; i++) if (a[i] >= (unsigned long long)NN) v = 0;
        g_is64[0] = v;
        const unsigned long long* b = (const unsigned long long*)et;
        v = 1;
        for (int i = 0; i < 8; i++) if (b[i] >= (unsigned long long)RR) v = 0;
        g_is64[1] = v;
    }
}

// ---------- bf16 hi/lo helpers ----------
__device__ __forceinline__ void f2bf(float x, unsigned short& h, unsigned short& l) {
    __nv_bfloat16 bh = __float2bfloat16(x);
    h = __bfloat16_as_ushort(bh);
    l = __bfloat16_as_ushort(__float2bfloat16(x - __bfloat162float(bh)));
}

__device__ __forceinline__ void mma16(float* d, const unsigned* a, const unsigned* b) {
    asm volatile("mma.sync.aligned.m16n8k16.row.col.f32.bf16.bf16.f32 "
        "{%0,%1,%2,%3}, {%4,%5,%6,%7}, {%8,%9}, {%0,%1,%2,%3};"
        : "+f"(d[0]), "+f"(d[1]), "+f"(d[2]), "+f"(d[3])
        : "r"(a[0]), "r"(a[1]), "r"(a[2]), "r"(a[3]), "r"(b[0]), "r"(b[1]));
}

#define APITCH 40
#define WPITCH 42

// ---------- bf16 3-split tensor-core GEMM ----------
__global__ void __launch_bounds__(256, 2) k_tgemm_bf(
    const float* __restrict__ A, const float* __restrict__ W, float* __restrict__ C,
    int K, int M, const float* __restrict__ bias, int doRelu, int accum)
{
    __shared__ unsigned short sAh[128*APITCH], sAl[128*APITCH];
    __shared__ unsigned short sWh[128*WPITCH], sWl[128*WPITCH];
    const int tid = threadIdx.x;
    const int w = tid >> 5, lane = tid & 31;
    const int g = lane >> 2, t = lane & 3;
    const int wr0 = (w >> 1) * 32, wc0 = (w & 1) * 64;
    const long long row0 = (long long)blockIdx.x * 128;
    const int col0 = blockIdx.y * 128;

    float acc[2][8][4];
#pragma unroll
    for (int a = 0; a < 2; a++)
#pragma unroll
        for (int b = 0; b < 8; b++)
#pragma unroll
            for (int c = 0; c < 4; c++) acc[a][b][c] = 0.f;

    for (int k0 = 0; k0 < K; k0 += 32) {
        __syncthreads();
#pragma unroll
        for (int i = 0; i < 4; i++) {
            int f = tid + 256 * i;
            int r = f >> 3, j = (f & 7) << 2;
            float4 v = *(const float4*)(A + (row0 + r) * K + k0 + j);
            unsigned short h, l;
            f2bf(v.x, h, l); sAh[r*APITCH+j+0] = h; sAl[r*APITCH+j+0] = l;
            f2bf(v.y, h, l); sAh[r*APITCH+j+1] = h; sAl[r*APITCH+j+1] = l;
            f2bf(v.z, h, l); sAh[r*APITCH+j+2] = h; sAl[r*APITCH+j+2] = l;
            f2bf(v.w, h, l); sAh[r*APITCH+j+3] = h; sAl[r*APITCH+j+3] = l;
        }
#pragma unroll
        for (int i = 0; i < 4; i++) {
            int f = tid + 256 * i;
            int kk = f >> 5, c = (f & 31) << 2;
            float4 v = *(const float4*)(W + (long long)(k0 + kk) * M + col0 + c);
            unsigned short h, l;
            f2bf(v.x, h, l); sWh[(c+0)*WPITCH+kk] = h; sWl[(c+0)*WPITCH+kk] = l;
            f2bf(v.y, h, l); sWh[(c+1)*WPITCH+kk] = h; sWl[(c+1)*WPITCH+kk] = l;
            f2bf(v.z, h, l); sWh[(c+2)*WPITCH+kk] = h; sWl[(c+2)*WPITCH+kk] = l;
            f2bf(v.w, h, l); sWh[(c+3)*WPITCH+kk] = h; sWl[(c+3)*WPITCH+kk] = l;
        }
        __syncthreads();
#pragma unroll
        for (int ks = 0; ks < 32; ks += 16) {
            unsigned ah[2][4], al[2][4];
#pragma unroll
            for (int mt = 0; mt < 2; mt++) {
                int rb = wr0 + mt * 16 + g;
                const unsigned short* p = &sAh[rb*APITCH + ks + 2*t];
                ah[mt][0] = *(const unsigned*)p;
                ah[mt][1] = *(const unsigned*)(p + 8*APITCH);
                ah[mt][2] = *(const unsigned*)(p + 8);
                ah[mt][3] = *(const unsigned*)(p + 8*APITCH + 8);
                const unsigned short* q = &sAl[rb*APITCH + ks + 2*t];
                al[mt][0] = *(const unsigned*)q;
                al[mt][1] = *(const unsigned*)(q + 8*APITCH);
                al[mt][2] = *(const unsigned*)(q + 8);
                al[mt][3] = *(const unsigned*)(q + 8*APITCH + 8);
            }
#pragma unroll
            for (int nt = 0; nt < 8; nt++) {
                int cn = wc0 + nt * 8 + g;
                unsigned bh[2], bl[2];
                const unsigned short* p = &sWh[cn*WPITCH + ks + 2*t];
                bh[0] = *(const unsigned*)p; bh[1] = *(const unsigned*)(p + 8);
                const unsigned short* q = &sWl[cn*WPITCH + ks + 2*t];
                bl[0] = *(const unsigned*)q; bl[1] = *(const unsigned*)(q + 8);
#pragma unroll
                for (int mt = 0; mt < 2; mt++) {
                    mma16(acc[mt][nt], ah[mt], bh);
                    mma16(acc[mt][nt], ah[mt], bl);
                    mma16(acc[mt][nt], al[mt], bh);
                }
            }
        }
    }
#pragma unroll
    for (int mt = 0; mt < 2; mt++) {
#pragma unroll
        for (int nt = 0; nt < 8; nt++) {
            int c = col0 + wc0 + nt * 8 + t * 2;
            long long r0 = row0 + wr0 + mt * 16 + g;
            float b0 = bias ? bias[c] : 0.f, b1 = bias ? bias[c+1] : 0.f;
            float v0 = acc[mt][nt][0] + b0, v1 = acc[mt][nt][1] + b1;
            float v2 = acc[mt][nt][2] + b0, v3 = acc[mt][nt][3] + b1;
            if (accum) {
                float2 o0 = *(const float2*)(C + r0 * M + c);
                float2 o1 = *(const float2*)(C + (r0 + 8) * M + c);
                v0 += o0.x; v1 += o0.y; v2 += o1.x; v3 += o1.y;
            }
            if (doRelu) {
                v0 = fmaxf(v0, 0.f); v1 = fmaxf(v1, 0.f);
                v2 = fmaxf(v2, 0.f); v3 = fmaxf(v3, 0.f);
            }
            *(float2*)(C + r0 * M + c)       = make_float2(v0, v1);
            *(float2*)(C + (r0 + 8) * M + c) = make_float2(v2, v3);
        }
    }
}

// ---------- small SIMT GEMM for 32-row rel_emb GEMMs ----------
__global__ void k_sgemm(const float* __restrict__ A, const float* __restrict__ W,
                        float* __restrict__ C, int rows, int K, int M)
{
    __shared__ float As[16][64];
    __shared__ float Ws[16][64];
    const int tid = threadIdx.x;
    const int tx = tid & 15, ty = tid >> 4;
    const int row0 = blockIdx.x * 64, col0 = blockIdx.y * 64;
    const int la_r = tid >> 2, la_k = (tid & 3) << 2;
    const int lw_k = tid >> 4, lw_c = (tid & 15) << 2;
    float acc[4][4];
#pragma unroll
    for (int i = 0; i < 4; i++)
#pragma unroll
        for (int j = 0; j < 4; j++) acc[i][j] = 0.f;
    for (int k0 = 0; k0 < K; k0 += 16) {
        float4 av = make_float4(0.f,0.f,0.f,0.f);
        if (row0 + la_r < rows)
            av = *(const float4*)(A + (size_t)(row0 + la_r) * K + (k0 + la_k));
        As[la_k+0][la_r] = av.x; As[la_k+1][la_r] = av.y;
        As[la_k+2][la_r] = av.z; As[la_k+3][la_r] = av.w;
        *(float4*)&Ws[lw_k][lw_c] = *(const float4*)(W + (size_t)(k0+lw_k)*M + col0 + lw_c);
        __syncthreads();
#pragma unroll
        for (int k = 0; k < 16; k++) {
            float4 a4 = *(const float4*)&As[k][ty<<2];
            float4 w4 = *(const float4*)&Ws[k][tx<<2];
            float ar[4] = {a4.x,a4.y,a4.z,a4.w};
            float wr[4] = {w4.x,w4.y,w4.z,w4.w};
#pragma unroll
            for (int i = 0; i < 4; i++)
#pragma unroll
                for (int j = 0; j < 4; j++) acc[i][j] += ar[i]*wr[j];
        }
        __syncthreads();
    }
#pragma unroll
    for (int i = 0; i < 4; i++) {
        int r = row0 + (ty<<2) + i;
        if (r < rows)
#pragma unroll
            for (int j = 0; j < 4; j++)
                C[(size_t)r*M + col0 + (tx<<2) + j] = acc[i][j];
    }
}

// ---------- bf16 tensor-core fused edge attention ----------
// mode 1: X = me;   out = relu(ie + a*V[src])
// mode 2: X = relu(P[src]+Q[et]+D[dst]) computed in-kernel, written to ie_out;
//         out = ie * a   (fused edge_init + input attention)
__global__ void __launch_bounds__(256, 2) k_edge_att_tc(
    const float* __restrict__ X, const float* __restrict__ Wm,
    const float* __restrict__ addvec, const void* idx_add, int sel_add,
    const void* idx_src, const float* __restrict__ w2,
    const float* __restrict__ ie, const float* __restrict__ V,
    float* __restrict__ outp, int mode,
    const float* __restrict__ Pm, const float* __restrict__ Qm,
    const float* __restrict__ Dm, const void* idx_et, const void* idx_dst,
    float* __restrict__ ie_out)
{
    __shared__ unsigned short sAh[128*APITCH], sAl[128*APITCH];
    __shared__ unsigned short sWh[128*WPITCH], sWl[128*WPITCH];
    __shared__ int ia_s[128], is_s[128], iet_s[128], idd_s[128];
    __shared__ float a_s[128], part_s[256], w2_s[128];

    const int tid = threadIdx.x;
    const int w = tid >> 5, lane = tid & 31;
    const int g = lane >> 2, t = lane & 3;
    const int wr0 = (w >> 1) * 32, wc0 = (w & 1) * 64;
    const long long e0 = (long long)blockIdx.x * 128;

    if (tid < 128) {
        ia_s[tid] = ld_idx(idx_add, e0 + tid, sel_add);
        is_s[tid] = ld_idx(idx_src, e0 + tid, 0);
        w2_s[tid] = w2[tid];
        if (mode == 2) {
            iet_s[tid] = ld_idx(idx_et, e0 + tid, 1);
            idd_s[tid] = ld_idx(idx_dst, e0 + tid, 0);
        }
    }

    float acc[2][8][4];
#pragma unroll
    for (int a = 0; a < 2; a++)
#pragma unroll
        for (int b = 0; b < 8; b++)
#pragma unroll
            for (int c = 0; c < 4; c++) acc[a][b][c] = 0.f;

    for (int k0 = 0; k0 < 128; k0 += 32) {
        __syncthreads();
        if (mode == 2) {
#pragma unroll
            for (int i = 0; i < 4; i++) {
                int f = tid + 256 * i;
                int r = f >> 3, j = (f & 7) << 2;
                int s = is_s[r], et = iet_s[r], dd = idd_s[r];
                float4 p = *(const float4*)(Pm + (size_t)s*HH + k0 + j);
                float4 q = *(const float4*)(Qm + (size_t)et*HH + k0 + j);
                float4 dv = *(const float4*)(Dm + (size_t)dd*HH + k0 + j);
                float4 v;
                v.x = fmaxf(p.x+q.x+dv.x, 0.f); v.y = fmaxf(p.y+q.y+dv.y, 0.f);
                v.z = fmaxf(p.z+q.z+dv.z, 0.f); v.w = fmaxf(p.w+q.w+dv.w, 0.f);
                *(float4*)(ie_out + (e0 + r)*HH + k0 + j) = v;
                unsigned short h, l;
                f2bf(v.x, h, l); sAh[r*APITCH+j+0] = h; sAl[r*APITCH+j+0] = l;
                f2bf(v.y, h, l); sAh[r*APITCH+j+1] = h; sAl[r*APITCH+j+1] = l;
                f2bf(v.z, h, l); sAh[r*APITCH+j+2] = h; sAl[r*APITCH+j+2] = l;
                f2bf(v.w, h, l); sAh[r*APITCH+j+3] = h; sAl[r*APITCH+j+3] = l;
            }
        } else {
#pragma unroll
            for (int i = 0; i < 4; i++) {
                int f = tid + 256 * i;
                int r = f >> 3, j = (f & 7) << 2;
                float4 v = *(const float4*)(X + (e0 + r) * HH + k0 + j);
                unsigned short h, l;
                f2bf(v.x, h, l); sAh[r*APITCH+j+0] = h; sAl[r*APITCH+j+0] = l;
                f2bf(v.y, h, l); sAh[r*APITCH+j+1] = h; sAl[r*APITCH+j+1] = l;
                f2bf(v.z, h, l); sAh[r*APITCH+j+2] = h; sAl[r*APITCH+j+2] = l;
                f2bf(v.w, h, l); sAh[r*APITCH+j+3] = h; sAl[r*APITCH+j+3] = l;
            }
        }
#pragma unroll
        for (int i = 0; i < 4; i++) {
            int f = tid + 256 * i;
            int kk = f >> 5, c = (f & 31) << 2;
            float4 v = *(const float4*)(Wm + (long long)(k0 + kk) * HH + c);
            unsigned short h, l;
            f2bf(v.x, h, l); sWh[(c+0)*WPITCH+kk] = h; sWl[(c+0)*WPITCH+kk] = l;
            f2bf(v.y, h, l); sWh[(c+1)*WPITCH+kk] = h; sWl[(c+1)*WPITCH+kk] = l;
            f2bf(v.z, h, l); sWh[(c+2)*WPITCH+kk] = h; sWl[(c+2)*WPITCH+kk] = l;
            f2bf(v.w, h, l); sWh[(c+3)*WPITCH+kk] = h; sWl[(c+3)*WPITCH+kk] = l;
        }
        __syncthreads();
#pragma unroll
        for (int ks = 0; ks < 32; ks += 16) {
            unsigned ah[2][4], al[2][4];
#pragma unroll
            for (int mt = 0; mt < 2; mt++) {
                int rb = wr0 + mt * 16 + g;
                const unsigned short* p = &sAh[rb*APITCH + ks + 2*t];
                ah[mt][0] = *(const unsigned*)p;
                ah[mt][1] = *(const unsigned*)(p + 8*APITCH);
                ah[mt][2] = *(const unsigned*)(p + 8);
                ah[mt][3] = *(const unsigned*)(p + 8*APITCH + 8);
                const unsigned short* q = &sAl[rb*APITCH + ks + 2*t];
                al[mt][0] = *(const unsigned*)q;
                al[mt][1] = *(const unsigned*)(q + 8*APITCH);
                al[mt][2] = *(const unsigned*)(q + 8);
                al[mt][3] = *(const unsigned*)(q + 8*APITCH + 8);
            }
#pragma unroll
            for (int nt = 0; nt < 8; nt++) {
                int cn = wc0 + nt * 8 + g;
                unsigned bh[2], bl[2];
                const unsigned short* p = &sWh[cn*WPITCH + ks + 2*t];
                bh[0] = *(const unsigned*)p; bh[1] = *(const unsigned*)(p + 8);
                const unsigned short* q = &sWl[cn*WPITCH + ks + 2*t];
                bl[0] = *(const unsigned*)q; bl[1] = *(const unsigned*)(q + 8);
#pragma unroll
                for (int mt = 0; mt < 2; mt++) {
                    mma16(acc[mt][nt], ah[mt], bh);
                    mma16(acc[mt][nt], ah[mt], bl);
                    mma16(acc[mt][nt], al[mt], bh);
                }
            }
        }
    }

    // attention scalar: per-row dot of relu(hidden + add) with w2
#pragma unroll
    for (int mt = 0; mt < 2; mt++) {
        int r0 = wr0 + mt * 16 + g, r1 = r0 + 8;
        const float2* ar0 = (const float2*)(addvec + (size_t)ia_s[r0] * HH);
        const float2* ar1 = (const float2*)(addvec + (size_t)ia_s[r1] * HH);
        float p0 = 0.f, p1 = 0.f;
#pragma unroll
        for (int nt = 0; nt < 8; nt++) {
            int c = wc0 + nt * 8 + t * 2;
            float w0 = w2_s[c], w1 = w2_s[c+1];
            float2 a0 = ar0[c >> 1], a1 = ar1[c >> 1];
            p0 += fmaxf(acc[mt][nt][0] + a0.x, 0.f) * w0
                + fmaxf(acc[mt][nt][1] + a0.y, 0.f) * w1;
            p1 += fmaxf(acc[mt][nt][2] + a1.x, 0.f) * w0
                + fmaxf(acc[mt][nt][3] + a1.y, 0.f) * w1;
        }
        p0 += __shfl_xor_sync(0xffffffffu, p0, 1);
        p0 += __shfl_xor_sync(0xffffffffu, p0, 2);
        p1 += __shfl_xor_sync(0xffffffffu, p1, 1);
        p1 += __shfl_xor_sync(0xffffffffu, p1, 2);
        if (t == 0) {
            part_s[r0 * 2 + (w & 1)] = p0;
            part_s[r1 * 2 + (w & 1)] = p1;
        }
    }
    __syncthreads();
    if (tid < 128) {
        float ps = part_s[tid * 2] + part_s[tid * 2 + 1];
        a_s[tid] = 1.f / (1.f + expf(-ps));
    }
    __syncthreads();

    // output epilogue
#pragma unroll
    for (int i = 0; i < 16; i++) {
        int f = tid + 256 * i;
        int r = f >> 5, q = (f & 31) << 2;
        size_t base = (size_t)(e0 + r) * HH + q;
        float4 iv = *(const float4*)(ie + base);
        float a = a_s[r];
        float4 o;
        if (mode == 1) {
            float4 v4 = *(const float4*)(V + (size_t)is_s[r] * HH + q);
            o.x = fmaxf(iv.x + a*v4.x, 0.f); o.y = fmaxf(iv.y + a*v4.y, 0.f);
            o.z = fmaxf(iv.z + a*v4.z, 0.f); o.w = fmaxf(iv.w + a*v4.w, 0.f);
        } else {
            o = make_float4(iv.x*a, iv.y*a, iv.z*a, iv.w*a);
        }
        *(float4*)(outp + base) = o;
    }
}

// ---------- CSR build ----------
__global__ void k_cnt_zero() {
    int t = blockIdx.x*256 + threadIdx.x;
    if (t < NN) g_cnt[t] = 0;
}
__global__ void k_count(const void* dstp) {
    int e = blockIdx.x*256 + threadIdx.x;
    if (e < NE) atomicAdd(&g_cnt[ld_idx(dstp, e, 0)], 1);
}
__global__ void __launch_bounds__(1024) k_scan() {
    __shared__ int wsum[32];
    int t = threadIdx.x;
    int lane = t & 31, wid = t >> 5;
    int base = t * 16;
    int loc[16];
    int s = 0;
#pragma unroll
    for (int i = 0; i < 16; i++) { loc[i] = g_cnt[base + i]; s += loc[i]; }
    int x = s;
#pragma unroll
    for (int off = 1; off < 32; off <<= 1) {
        int v = __shfl_up_sync(0xffffffffu, x, off);
        if (lane >= off) x += v;
    }
    if (lane == 31) wsum[wid] = x;
    __syncthreads();
    if (wid == 0) {
        int y = wsum[lane];
#pragma unroll
        for (int off = 1; off < 32; off <<= 1) {
            int v = __shfl_up_sync(0xffffffffu, y, off);
            if (lane >= off) y += v;
        }
        wsum[lane] = y;
    }
    __syncthreads();
    int run = x - s + (wid ? wsum[wid - 1] : 0);
#pragma unroll
    for (int i = 0; i < 16; i++) {
        g_off[base + i] = run;
        g_cur[base + i] = run;
        run += loc[i];
    }
    if (t == 1023) g_off[NN] = run;
}
__global__ void k_fill(const void* dstp) {
    int e = blockIdx.x*256 + threadIdx.x;
    if (e < NE) {
        int d = ld_idx(dstp, e, 0);
        int pos = atomicAdd(&g_cur[d], 1);
        g_eid[pos] = e;
    }
}

// ---------- CSR gather aggregation ----------
__global__ void __launch_bounds__(128) k_gather(const float* __restrict__ me,
                                                const float* __restrict__ addb,
                                                float* __restrict__ out)
{
    int n = blockIdx.x, j = threadIdx.x;
    int o0 = g_off[n], o1 = g_off[n+1];
    float s = addb ? addb[(size_t)n*HH + j] : 0.f;
    for (int i = o0; i < o1; i++) {
        int e = g_eid[i];
        s += me[(size_t)e*HH + j];
    }
    out[(size_t)n*HH + j] = s;
}

// ---------- GRU prep ----------
__global__ void k_msg(const float* __restrict__ gru_bias) {
    int t = blockIdx.x*256 + threadIdx.x;
    g_msg[t] = fmaxf(g_nodeh[t] + gru_bias[t & 127], 0.f);
}
__global__ void k_h0() {
    int b = blockIdx.x, j = threadIdx.x;
    float m = -1e30f;
    for (int s = 0; s < SS; s++)
        m = fmaxf(m, g_nodeh[((size_t)(b*SS + s))*HH + j]);
    g_h0[b*HH + j] = m;
}
__global__ void k_twih(const float* __restrict__ Wih) {
    int t = blockIdx.x*256 + threadIdx.x;
    if (t < 2*384*128) {
        int d = t / (384*128), rem = t % (384*128);
        int o = rem / 128, k = rem % 128;
        g_WihT[d*384*128 + k*384 + o] = Wih[t];
    }
}
__global__ void k_msg2() {
    int t = blockIdx.x*256 + threadIdx.x;
    int r = t >> 7, j = t & 127;
    int b = r >> 1, s = r & 1;
    g_msg2[t] = g_msg[((size_t)(b*SS + s))*HH + j];
}

__global__ void __launch_bounds__(384) k_gru(const float* __restrict__ Whh,
                                             const float* __restrict__ bhh)
{
    const int b = blockIdx.x, dir = blockIdx.y;
    const int o = threadIdx.x;
    float w[128];
    const float* wr = Whh + ((size_t)dir*384 + o)*128;
#pragma unroll
    for (int k = 0; k < 128; k += 4) {
        float4 v = *(const float4*)(wr + k);
        w[k]=v.x; w[k+1]=v.y; w[k+2]=v.z; w[k+3]=v.w;
    }
    const float bh = bhh[dir*384 + o];
    __shared__ float h_s[128];
    __shared__ float gh_s[384];
    if (o < 128) h_s[o] = g_h0[b*128 + o];
    __syncthreads();
    const int nsteps = (dir == 0) ? 2 : SS;
    for (int i2 = 0; i2 < nsteps; i2++) {
        int t = (dir == 0) ? i2 : (SS - 1 - i2);
        float gh = bh;
#pragma unroll
        for (int k = 0; k < 128; k += 4) {
            float4 hv = *(const float4*)&h_s[k];
            gh += w[k]*hv.x + w[k+1]*hv.y + w[k+2]*hv.z + w[k+3]*hv.w;
        }
        gh_s[o] = gh;
        __syncthreads();
        if (o < 128) {
            const float* gi = (dir == 0) ? (g_gif + (size_t)(b*2 + t)*384)
                                         : (g_gi  + (size_t)(b*SS + t)*384);
            float ir = gi[o], iz = gi[128+o], inn = gi[256+o];
            float r = 1.f/(1.f+expf(-(ir + gh_s[o])));
            float z = 1.f/(1.f+expf(-(iz + gh_s[128+o])));
            float n = tanhf(inn + r*gh_s[256+o]);
            float hnew = (1.f-z)*n + z*h_s[o];
            if (dir == 0) {
                if (i2 == 0)      g_y[0*BB*128 + b*128 + o] = hnew;
                else if (i2 == 1) g_y[1*BB*128 + b*128 + o] = hnew;
            } else {
                if (i2 == SS-1)      g_y[2*BB*128 + b*128 + o] = hnew;
                else if (i2 == SS-2) g_y[3*BB*128 + b*128 + o] = hnew;
            }
            h_s[o] = hnew;
        }
        __syncthreads();
    }
}

__global__ void k_final(const float* __restrict__ Wo, const float* __restrict__ bo,
                        const float* __restrict__ rel_emb, const void* trg,
                        const float* __restrict__ l1W, const float* __restrict__ l1b,
                        const float* __restrict__ l2W, const float* __restrict__ l2b,
                        float* __restrict__ out)
{
    const int b = blockIdx.x, j = threadIdx.x;
    __shared__ float conv[128];
    __shared__ float s16[16];
    float hh = bo[j], ht = bo[j];
    const float* yf0 = g_y + 0*BB*128 + b*128;
    const float* yf1 = g_y + 1*BB*128 + b*128;
    const float* yb0 = g_y + 2*BB*128 + b*128;
    const float* yb1 = g_y + 3*BB*128 + b*128;
    for (int k = 0; k < 128; k++) {
        float wk = Wo[k*128 + j];
        hh += yf0[k]*wk; ht += yf1[k]*wk;
    }
    for (int k = 0; k < 128; k++) {
        float wk = Wo[(128+k)*128 + j];
        hh += yb0[k]*wk; ht += yb1[k]*wk;
    }
    hh = fmaxf(hh, 0.f); ht = fmaxf(ht, 0.f);
    int tr = ld_idx(trg, b, 1);
    conv[j] = tanhf(hh + rel_emb[tr*128 + j] - ht);
    __syncthreads();
    if (j < 16) {
        float s = l1b[j];
        for (int k = 0; k < 128; k++) s += conv[k]*l1W[k*16 + j];
        s16[j] = s;
    }
    __syncthreads();
    if (j == 0) {
        float o = l2b[0];
        for (int i = 0; i < 16; i++) o += s16[i]*l2W[i];
        out[b] = o;
    }
}

extern "C" void kernel_launch(void* const* d_in, const int* in_sizes, int n_in,
                              void* d_out, int out_size)
{
    const float* node_feat = (const float*)d_in[0];
    const float* rel_emb   = (const float*)d_in[1];
    const float* W_i_node  = (const float*)d_in[2];
    const float* W_i_edge  = (const float*)d_in[3];
    const float* W_att_in1 = (const float*)d_in[4];
    const float* W_att_in2 = (const float*)d_in[5];
    const float* W_h_node  = (const float*)d_in[6];
    const float* W_h_edge  = (const float*)d_in[7];
    const float* W_att1    = (const float*)d_in[8];
    const float* W_att2    = (const float*)d_in[9];
    const float* comm_W    = (const float*)d_in[10];
    const float* W_o       = (const float*)d_in[11];
    const float* b_o       = (const float*)d_in[12];
    const float* gru_bias  = (const float*)d_in[13];
    const float* gru_Wih   = (const float*)d_in[14];
    const float* gru_Whh   = (const float*)d_in[15];
    const float* gru_bih   = (const float*)d_in[16];
    const float* gru_bhh   = (const float*)d_in[17];
    const float* lin1_W    = (const float*)d_in[18];
    const float* lin1_b    = (const float*)d_in[19];
    const float* lin2_W    = (const float*)d_in[20];
    const float* lin2_b    = (const float*)d_in[21];
    const void*  src       = d_in[22];
    const void*  dst       = d_in[23];
    const void*  etype     = d_in[24];
    const void*  elabel    = d_in[25];
    const void*  trg       = d_in[26];
    float* out = (float*)d_out;

    float *ge_ie, *ge_me, *ge_in, *ge_P, *ge_D, *ge_U, *ge_mn, *ge_agg, *ge_V;
    float *ge_nodeh, *ge_msg, *ge_scr, *ge_gi, *ge_gif, *ge_msg2, *ge_WihT, *ge_Qrel, *ge_Qd;
    cudaGetSymbolAddress((void**)&ge_ie, g_ie);
    cudaGetSymbolAddress((void**)&ge_me, g_me);
    cudaGetSymbolAddress((void**)&ge_in, g_in);
    cudaGetSymbolAddress((void**)&ge_P, g_P);
    cudaGetSymbolAddress((void**)&ge_D, g_D);
    cudaGetSymbolAddress((void**)&ge_U, g_U);
    cudaGetSymbolAddress((void**)&ge_mn, g_mn);
    cudaGetSymbolAddress((void**)&ge_agg, g_agg);
    cudaGetSymbolAddress((void**)&ge_V, g_V);
    cudaGetSymbolAddress((void**)&ge_nodeh, g_nodeh);
    cudaGetSymbolAddress((void**)&ge_msg, g_msg);
    cudaGetSymbolAddress((void**)&ge_scr, g_scr);
    cudaGetSymbolAddress((void**)&ge_gi, g_gi);
    cudaGetSymbolAddress((void**)&ge_gif, g_gif);
    cudaGetSymbolAddress((void**)&ge_msg2, g_msg2);
    cudaGetSymbolAddress((void**)&ge_WihT, g_WihT);
    cudaGetSymbolAddress((void**)&ge_Qrel, g_Qrel);
    cudaGetSymbolAddress((void**)&ge_Qd, g_Qd);

    k_detect<<<1, 32>>>(src, etype);

    // CSR of dst
    k_cnt_zero<<<NN/256, 256>>>();
    k_count<<<NE/256, 256>>>(dst);
    k_scan<<<1, 1024>>>();
    k_fill<<<NE/256, 256>>>(dst);

    // node-side GEMMs (bf16 3-split tensor cores)
    k_tgemm_bf<<<dim3(NN/128, 1), 256>>>(node_feat, W_i_edge,           ge_P, 64, 128, NULL, 0, 0);
    k_tgemm_bf<<<dim3(NN/128, 1), 256>>>(node_feat, W_i_edge + 192*128, ge_D, 64, 128, NULL, 0, 0);
    k_tgemm_bf<<<dim3(NN/128, 1), 256>>>(node_feat, W_i_node,           ge_in, 64, 128, NULL, 1, 0);
    // small rel_emb GEMMs (rows=32, SIMT fp32)
    k_sgemm<<<dim3(1,2), 256>>>(rel_emb, W_i_edge + 64*128,         ge_Qrel,        RR, 128, 128);
    k_sgemm<<<dim3(1,2), 256>>>(rel_emb, W_att1 + 128*128,          ge_Qd,          RR, 128, 128);
    k_sgemm<<<dim3(1,2), 256>>>(rel_emb, W_att1 + 32768 + 128*128,  ge_Qd + RR*128, RR, 128, 128);

    // fused edge_init + input attention (mode 2)
    k_tgemm_bf<<<dim3(NN/128, 1), 256>>>(ge_in, W_att_in1, ge_U, 128, 128, NULL, 0, 0);
    k_edge_att_tc<<<NE/128, 256>>>(NULL, W_att_in1 + 128*128, ge_U, src, 0, src,
                                   W_att_in2, ge_ie, NULL, ge_me, 2,
                                   ge_P, ge_Qrel, ge_D, etype, dst, ge_ie);

    // two message-passing depths
    for (int d = 0; d < 2; d++) {
        const float* mn_old = (d == 0) ? ge_in : ge_mn;
        k_gather<<<NN, 128>>>(ge_me, mn_old, ge_scr);
        k_tgemm_bf<<<dim3(NN/128, 1), 256>>>(ge_scr, W_h_node + d*16384, ge_mn, 128, 128, NULL, 1, 0);
        k_tgemm_bf<<<dim3(NN/128, 1), 256>>>(ge_mn, W_h_edge + d*16384, ge_V, 128, 128, NULL, 0, 0);
        k_edge_att_tc<<<NE/128, 256>>>(ge_me, W_att1 + d*32768, ge_Qd + d*RR*128, elabel, 1,
                                       src, W_att2 + d*128, ge_ie, ge_V, ge_me, 1,
                                       NULL, NULL, NULL, NULL, NULL, NULL);
    }

    // readout aggregation + comm
    k_gather<<<NN, 128>>>(ge_me, NULL, ge_agg);
    k_tgemm_bf<<<dim3(NN/128, 1), 256>>>(ge_agg, comm_W,           ge_nodeh, 128, 128, NULL, 0, 0);
    k_tgemm_bf<<<dim3(NN/128, 1), 256>>>(ge_mn,  comm_W + 128*128, ge_nodeh, 128, 128, NULL, 0, 1);
    k_tgemm_bf<<<dim3(NN/128, 1), 256>>>(ge_in,  comm_W + 256*128, ge_nodeh, 128, 128, NULL, 0, 1);

    // GRU
    k_msg<<<NN*128/256, 256>>>(gru_bias);
    k_h0<<<BB, 128>>>();
    k_twih<<<(2*384*128 + 255)/256, 256>>>(gru_Wih);
    k_msg2<<<128*128/256, 256>>>();
    k_tgemm_bf<<<dim3(1, 3), 256>>>(ge_msg2, ge_WihT,           ge_gif, 128, 384, gru_bih,       0, 0);
    k_tgemm_bf<<<dim3(NN/128, 3), 256>>>(ge_msg, ge_WihT + 384*128, ge_gi, 128, 384, gru_bih + 384, 0, 0);
    k_gru<<<dim3(BB, 2), 384>>>(gru_Whh, gru_bhh);

    k_final<<<BB, 128>>>(W_o, b_o, rel_emb, trg, lin1_W, lin1_b, lin2_W, lin2_b, out);
}